// round 12
// baseline (speedup 1.0000x reference)
#include <cuda_runtime.h>
#include <math.h>
#include <cstdint>

// 16-CTA cluster, persistent, warp-specialized:
//   CRIT (warps 0-7): the serial dependency chain a1->acc2->a2->a3->d3->o2->o1->acc1(t+1)
//   HELP (warps 8-15): x/tg prefetch, z=m1*x_next + gamma=x_t*x_{t+1} lookahead,
//                      ALL weight updates (W3,W2c,W2r,W1) + bias updates + norms.
// Handoffs: bar.arrive/bar.sync id=3 (d3,o2,a2 ready), id=4 (o1 ready, m2r free).
// acc1(t+1) = q1*z - LR*gamma*o1  (rank-1 lookahead: W1 MV off the critical path).
// R12 fix: BAR1 between o2 write and o1's read of the full o2 vector (the R11 race).

#define NC 16
#define T  512
#define Dd 1024
#define Hh 256
#define Oo 64
#define NSTEPS 1024
#define LRc 0.01f
#define EPSc 1e-8f
#define C1 16
#define TOTAL_OUT (Dd * Hh + Hh * Hh + Hh * Oo)   // 344064

// ---- SMEM layout (float offsets) ----
#define OFF_M1    0        // [C1][Dd] W1 col slice           16384
#define OFF_M2C   16384    // [C1][Hh] W2 col slice            4096
#define OFF_M2R   20480    // [C1][Hh] W2 row slice            4096
#define OFF_M3    24576    // [Oo][Hh] W3 full [j][i]         16384
#define OFF_X     40960    // [2][Dd]                          2048
#define OFF_TG    43008    // [2][Oo]                           128
#define OFF_ACC1R 43136    // [Hh] pushed raw l1 preact         256
#define OFF_ACC2R 43392    // [Hh] pushed raw l2 preact         256
#define OFF_O1F   43648    // [Hh] pushed o1 full               256
#define OFF_SPART 43904    // [NC][2] pushed ss1,ss2             32
#define OFF_A1F   43936    // [Hh]                              256
#define OFF_A2C   44192    // [Hh]                              256
#define OFF_A3RAW 44448    // [Oo]                               64
#define OFF_D3    44512    // [Oo]                               64
#define OFF_O2    44576    // [Hh]                              256
#define OFF_ZBUF  44832    // [C1]                               16
#define OFF_MB1   44848    // [Hh]                              256
#define OFF_MB2   45104    // [Hh]                              256
#define OFF_MB3   45360    // [Oo]                               64
#define OFF_STG   45424    // [C1]                               16
#define OFF_O1OWN 45440    // [C1]                               16
#define OFF_CRED  45456    // [16] CRIT scratch                  16
#define OFF_HA    45472    // [16] HELP scratch ss3              16
#define OFF_HB    45488    // [16] bn3                           16
#define OFF_HC    45504    // [16] bn2                           16
#define OFF_HD    45520    // [16] ss2                           16
#define OFF_HE    45536    // [16] ss1                           16
#define OFF_SQ    45552    // q1,q2,q3,qb1,qb2,qb3                8
#define OFF_SGAM  45560    // gamma (+pad)                        8
#define SMEM_FLOATS 45568
#define SMEM_BYTES (SMEM_FLOATS * 4)

__device__ __forceinline__ uint32_t smem_u32(const void* p) {
    uint32_t a;
    asm("{ .reg .u64 t; cvta.to.shared.u64 t, %1; cvt.u32.u64 %0, t; }"
        : "=r"(a) : "l"(p));
    return a;
}
__device__ __forceinline__ void st_peer(uint32_t laddr, uint32_t rank, float v) {
    uint32_t r;
    asm volatile("mapa.shared::cluster.u32 %0, %1, %2;" : "=r"(r) : "r"(laddr), "r"(rank));
    asm volatile("st.shared::cluster.f32 [%0], %1;" :: "r"(r), "f"(v) : "memory");
}
#define CLUSTER_SYNC() do { \
    asm volatile("barrier.cluster.arrive.aligned;" ::: "memory"); \
    asm volatile("barrier.cluster.wait.aligned;" ::: "memory");   \
} while (0)
#define BAR1()        asm volatile("bar.sync 1, 256;" ::: "memory")
#define BAR2()        asm volatile("bar.sync 2, 256;" ::: "memory")
#define BAR3_ARRIVE() asm volatile("bar.arrive 3, 512;" ::: "memory")
#define BAR3_SYNC()   asm volatile("bar.sync 3, 512;" ::: "memory")
#define BAR4_ARRIVE() asm volatile("bar.arrive 4, 512;" ::: "memory")
#define BAR4_SYNC()   asm volatile("bar.sync 4, 512;" ::: "memory")

__device__ __forceinline__ float warp_sum(float v) {
    #pragma unroll
    for (int o = 16; o; o >>= 1) v += __shfl_xor_sync(0xffffffffu, v, o);
    return v;
}
__device__ __forceinline__ float sigmoidf(float p) { return 1.f / (1.f + expf(-p)); }
__device__ __forceinline__ float sanitize(float v) { return isfinite(v) ? v : 0.f; }
__device__ __forceinline__ float dot4(float4 a, float4 b) {
    return a.x * b.x + a.y * b.y + a.z * b.z + a.w * b.w;
}

__global__ void __launch_bounds__(T, 1)
train_kernel(const float* __restrict__ X, const float* __restrict__ Tg,
             const float* __restrict__ W1g, const float* __restrict__ b1g,
             const float* __restrict__ W2g, const float* __restrict__ b2g,
             const float* __restrict__ W3g, const float* __restrict__ b3g,
             float* __restrict__ out, int out_size)
{
    extern __shared__ float sm[];
    float* m1    = sm + OFF_M1;
    float* m2c   = sm + OFF_M2C;
    float* m2r   = sm + OFF_M2R;
    float* m3    = sm + OFF_M3;
    float* xb    = sm + OFF_X;
    float* tgb   = sm + OFF_TG;
    float* acc1r = sm + OFF_ACC1R;
    float* acc2r = sm + OFF_ACC2R;
    float* o1f   = sm + OFF_O1F;
    float* spart = sm + OFF_SPART;
    float* a1f   = sm + OFF_A1F;
    float* a2c   = sm + OFF_A2C;
    float* a3raw = sm + OFF_A3RAW;
    float* d3c   = sm + OFF_D3;
    float* o2    = sm + OFF_O2;
    float* zbuf  = sm + OFF_ZBUF;
    float* mb1   = sm + OFF_MB1;
    float* mb2   = sm + OFF_MB2;
    float* mb3   = sm + OFF_MB3;
    float* stg   = sm + OFF_STG;
    float* o1own = sm + OFF_O1OWN;
    float* cred  = sm + OFF_CRED;
    float* hA    = sm + OFF_HA;
    float* hB    = sm + OFF_HB;
    float* hC    = sm + OFF_HC;
    float* hD    = sm + OFF_HD;
    float* hE    = sm + OFF_HE;
    float* sq    = sm + OFF_SQ;
    float* sgam  = sm + OFF_SGAM;

    const int tid = threadIdx.x;
    const int w = tid >> 5, lane = tid & 31;

    uint32_t me;
    asm("mov.u32 %0, %%cluster_ctarank;" : "=r"(me));
    const uint32_t sbase = smem_u32(sm);
    const uint32_t ACC1A = sbase + OFF_ACC1R * 4;
    const uint32_t ACC2A = sbase + OFF_ACC2R * 4;
    const uint32_t O1FA  = sbase + OFF_O1F * 4;
    const uint32_t SPA   = sbase + OFF_SPART * 4;

    // ================= init =================
    for (int idx = tid; idx < C1 * Dd; idx += T) {
        int c = idx & 15, r = idx >> 4;
        m1[c * Dd + r] = W1g[r * Hh + me * C1 + c];
    }
    for (int idx = tid; idx < C1 * Hh; idx += T) {
        int c = idx & 15, i = idx >> 4;
        m2c[c * Hh + i] = W2g[i * Hh + me * C1 + c];
    }
    for (int idx = tid; idx < C1 * Hh; idx += T) {
        int r = idx >> 8, j = idx & 255;
        m2r[r * Hh + j] = W2g[(me * C1 + r) * Hh + j];
    }
    for (int idx = tid; idx < Oo * Hh; idx += T)
        m3[idx] = W3g[(idx & 255) * Oo + (idx >> 8)];
    if (tid < Hh) { mb1[tid] = b1g[tid]; mb2[tid] = b2g[tid]; o1f[tid] = 0.f; }
    if (tid < Oo) mb3[tid] = b3g[tid];
    if (tid < 8)  sq[tid] = 1.f;
    if (tid < 32) spart[tid] = 0.f;
    if (tid < 256) ((float4*)xb)[tid] = ((const float4*)X)[tid];
    else if (tid < 320) tgb[tid - 256] = Tg[tid - 256];
    __syncthreads();

    // prologue: acc1raw(0) direct MV (all 16 warps)
    {
        const float4* c4 = (const float4*)(m1 + w * Dd);
        const float4* x4 = (const float4*)xb;
        float acc = 0.f;
        #pragma unroll
        for (int k = 0; k < 8; k++) acc += dot4(c4[k * 32 + lane], x4[k * 32 + lane]);
        acc = warp_sum(acc);
        if (lane == 0) stg[w] = acc;
    }
    __syncthreads();
    CLUSTER_SYNC();
    if (tid < 256) st_peer(ACC1A + ((me * C1 + (tid >> 4)) << 2), tid & 15, stg[tid >> 4]);
    CLUSTER_SYNC();   // "SYNC1" of step 0

    for (int step = 0; step < NSTEPS; ++step) {
        const int par = step & 1;
        const float* xcur = xb + par * Dd;
        float* xnext = xb + (par ^ 1) * Dd;

        if (tid < 256) {
            // =============== CRIT seg1 ===============
            if (w == 0 && step > 0) {
                float s1 = (lane < 16) ? spart[2 * lane] : 0.f;
                s1 = warp_sum(s1);
                float s2 = (lane < 16) ? spart[2 * lane + 1] : 0.f;
                s2 = warp_sum(s2);
                if (lane == 0) {
                    sq[0] = 1.f / fmaxf(sqrtf(s1), EPSc);
                    sq[1] = 1.f / fmaxf(sqrtf(s2), EPSc);
                }
            }
            if (step > 0) {   // b1 update from prev step's o1
                float bv = sq[3] * mb1[tid] - LRc * o1f[tid];
                mb1[tid] = bv;
                float p = warp_sum(bv * bv);
                if (lane == 0) cred[w] = p;
            }
            BAR1();
            if (w == 0 && step > 0) {
                float b = (lane < 8) ? cred[lane] : 0.f;
                b = warp_sum(b);
                if (lane == 0) sq[3] = 1.f / fmaxf(sqrtf(b), EPSc);
            }
            BAR1();
            const float q1 = sq[0], qb1 = sq[3];
            a1f[tid] = sigmoidf(q1 * acc1r[tid] + qb1 * mb1[tid]);
            BAR1();
            {   // acc2: warp w -> cols 2w, 2w+1
                const float4* a14 = (const float4*)a1f;
                const float4* cA = (const float4*)(m2c + (2 * w) * Hh);
                const float4* cB = (const float4*)(m2c + (2 * w + 1) * Hh);
                float aA = 0.f, aB = 0.f;
                #pragma unroll
                for (int k = 0; k < 2; k++) {
                    float4 av = a14[k * 32 + lane];
                    aA += dot4(cA[k * 32 + lane], av);
                    aB += dot4(cB[k * 32 + lane], av);
                }
                aA = warp_sum(aA); aB = warp_sum(aB);
                if (lane == 0) { stg[2 * w] = aA; stg[2 * w + 1] = aB; }
            }
            BAR1();
            st_peer(ACC2A + ((me * C1 + (tid >> 4)) << 2), tid & 15, stg[tid >> 4]);
        } else {
            // =============== HELP seg1: prefetch, z, gamma ===============
            int t2 = tid - 256, w2 = t2 >> 5, l2 = t2 & 31;
            if (step + 1 < NSTEPS) {
                ((float4*)xnext)[t2] = ((const float4*)(X + (step + 1) * Dd))[t2];
                if (t2 < Oo) tgb[(par ^ 1) * Oo + t2] = Tg[(step + 1) * Oo + t2];
            }
            BAR2();
            {   // z[c] = m1_pre . x_next ; 16 threads per col
                int c = t2 >> 4, seg = t2 & 15;
                const float4* mc4 = (const float4*)(m1 + c * Dd);
                const float4* xn4 = (const float4*)xnext;
                float z = 0.f;
                #pragma unroll
                for (int q = 0; q < 16; q++) z += dot4(mc4[seg * 16 + q], xn4[seg * 16 + q]);
                #pragma unroll
                for (int o = 8; o; o >>= 1) z += __shfl_xor_sync(0xffffffffu, z, o);
                if (seg == 0) zbuf[c] = z;
            }
            {   // gamma = x_t . x_next
                float g = dot4(((const float4*)xcur)[t2], ((const float4*)xnext)[t2]);
                g = warp_sum(g);
                if (l2 == 0) hA[w2] = g;
            }
            BAR2();
            if (w2 == 0) {
                float g = (l2 < 8) ? hA[l2] : 0.f;
                g = warp_sum(g);
                if (l2 == 0) sgam[0] = g;
            }
        }
        CLUSTER_SYNC();   // SYNC2: acc2 delivered

        if (tid < 256) {
            // =============== CRIT chain ===============
            const float q1 = sq[0], q2 = sq[1], q3u = sq[2];
            const float qb2 = sq[4];
            a2c[tid] = sigmoidf(q2 * acc2r[tid] + qb2 * mb2[tid]);
            BAR1();
            {   // a3 raw: warp w -> j = w + 8s
                const float4* a24 = (const float4*)a2c;
                float acc[8];
                #pragma unroll
                for (int s = 0; s < 8; s++) {
                    const float4* r4 = (const float4*)(m3 + (w + 8 * s) * Hh);
                    float a = 0.f;
                    #pragma unroll
                    for (int k = 0; k < 2; k++)
                        a += dot4(r4[k * 32 + lane], a24[k * 32 + lane]);
                    acc[s] = a;
                }
                #pragma unroll
                for (int o = 16; o; o >>= 1) {
                    #pragma unroll
                    for (int s = 0; s < 8; s++)
                        acc[s] += __shfl_xor_sync(0xffffffffu, acc[s], o);
                }
                if (lane == 0) {
                    #pragma unroll
                    for (int s = 0; s < 8; s++) a3raw[w + 8 * s] = acc[s];
                }
            }
            BAR1();
            if (w == 0) {   // sigmoid + softmax + d3
                const float qb3 = sq[5];
                float a30 = sigmoidf(q3u * a3raw[lane] + qb3 * mb3[lane]);
                float a31 = sigmoidf(q3u * a3raw[lane + 32] + qb3 * mb3[lane + 32]);
                const float* tgc = tgb + par * Oo;
                float t0 = tgc[lane], t1 = tgc[lane + 32];
                float m = fmaxf(-a30, -a31);
                #pragma unroll
                for (int o = 16; o; o >>= 1) m = fmaxf(m, __shfl_xor_sync(0xffffffffu, m, o));
                float e0 = expf(-a30 - m), e1 = expf(-a31 - m);
                float s = warp_sum(e0 + e1);
                float inv = 1.f / s;
                d3c[lane]      = (t0 - e0 * inv) * a30 * (1.f - a30);
                d3c[lane + 32] = (t1 - e1 * inv) * a31 * (1.f - a31);
            }
            BAR1();
            {   // o2 (pre-update m3)
                const float* col = m3 + tid;
                float r0 = 0.f, r1 = 0.f, r2 = 0.f, r3 = 0.f;
                #pragma unroll
                for (int j = 0; j < Oo; j += 4) {
                    r0 += col[(j + 0) * Hh] * d3c[j + 0];
                    r1 += col[(j + 1) * Hh] * d3c[j + 1];
                    r2 += col[(j + 2) * Hh] * d3c[j + 2];
                    r3 += col[(j + 3) * Hh] * d3c[j + 3];
                }
                float raw = (r0 + r1) + (r2 + r3);
                float a = a2c[tid];
                o2[tid] = q3u * raw * a * (1.f - a);
            }
            BAR3_ARRIVE();   // handoff A: a2,d3,o2 ready (HELP waits on full bar)
            BAR1();          // R12 FIX: o2 fully written before o1 reads all of it
            {   // o1: warp w -> rows 2w, 2w+1 (pre-update m2r)
                const float4* o24 = (const float4*)o2;
                const float4* rA = (const float4*)(m2r + (2 * w) * Hh);
                const float4* rB = (const float4*)(m2r + (2 * w + 1) * Hh);
                float aA = 0.f, aB = 0.f;
                #pragma unroll
                for (int k = 0; k < 2; k++) {
                    float4 ov = o24[k * 32 + lane];
                    aA += dot4(rA[k * 32 + lane], ov);
                    aB += dot4(rB[k * 32 + lane], ov);
                }
                aA = warp_sum(aA); aB = warp_sum(aB);
                if (lane == 0) {
                    float a1A = a1f[me * C1 + 2 * w];
                    float a1B = a1f[me * C1 + 2 * w + 1];
                    o1own[2 * w]     = q2 * aA * a1A * (1.f - a1A);
                    o1own[2 * w + 1] = q2 * aB * a1B * (1.f - a1B);
                }
            }
            BAR1();
            BAR4_ARRIVE();   // handoff B: o1 ready, m2r free
            {   // lookahead correction + end-of-step pushes
                int j = tid >> 4, p = tid & 15;
                float val = q1 * zbuf[j] - (LRc * sgam[0]) * o1own[j];
                st_peer(ACC1A + ((me * C1 + j) << 2), p, val);
                st_peer(O1FA + ((me * C1 + j) << 2), p, o1own[j]);
            }
        } else {
            // =============== HELP updates ===============
            int t2 = tid - 256, w2 = t2 >> 5, l2 = t2 & 31;
            const float q1 = sq[0], q2 = sq[1], q3old = sq[2];
            const float qb2 = sq[4], qb3 = sq[5];
            BAR3_SYNC();   // wait a2,d3,o2
            float ss3 = 0.f, bn3 = 0.f, bn2 = 0.f;
            {   // W3 update + ss3
                float4* m34 = (float4*)m3;
                const float4* a24 = (const float4*)a2c;
                #pragma unroll
                for (int k = 0; k < 16; k++) {
                    int e4 = t2 + 256 * k;
                    int j = e4 >> 6, i4 = e4 & 63;
                    float dv = LRc * d3c[j];
                    float4 wv = m34[e4], av = a24[i4];
                    wv.x = q3old * wv.x - dv * av.x;
                    wv.y = q3old * wv.y - dv * av.y;
                    wv.z = q3old * wv.z - dv * av.z;
                    wv.w = q3old * wv.w - dv * av.w;
                    m34[e4] = wv;
                    ss3 += dot4(wv, wv);
                }
            }
            if (t2 < Oo) {   // b3
                float v = qb3 * mb3[t2] - LRc * d3c[t2];
                mb3[t2] = v; bn3 = v * v;
            }
            {   // b2
                float v = qb2 * mb2[t2] - LRc * o2[t2];
                mb2[t2] = v; bn2 = v * v;
            }
            float ss2 = 0.f;
            {   // W2 col update + ss2
                float4* c4 = (float4*)m2c;
                const float4* a14 = (const float4*)a1f;
                #pragma unroll
                for (int k = 0; k < 4; k++) {
                    int e4 = t2 + 256 * k;
                    int c = e4 >> 6, i4 = e4 & 63;
                    float sv = LRc * o2[me * C1 + c];
                    float4 wv = c4[e4], av = a14[i4];
                    wv.x = q2 * wv.x - sv * av.x;
                    wv.y = q2 * wv.y - sv * av.y;
                    wv.z = q2 * wv.z - sv * av.z;
                    wv.w = q2 * wv.w - sv * av.w;
                    c4[e4] = wv;
                    ss2 += dot4(wv, wv);
                }
            }
            ss3 = warp_sum(ss3); bn3 = warp_sum(bn3);
            bn2 = warp_sum(bn2); ss2 = warp_sum(ss2);
            if (l2 == 0) { hA[w2] = ss3; hB[w2] = bn3; hC[w2] = bn2; hD[w2] = ss2; }
            BAR2();
            if (w2 == 0) {
                float v = (l2 < 8) ? hA[l2] : 0.f; v = warp_sum(v);
                if (l2 == 0) sq[2] = 1.f / fmaxf(sqrtf(v), EPSc);
            } else if (w2 == 1) {
                float v = (l2 < 8) ? hB[l2] : 0.f; v = warp_sum(v);
                if (l2 == 0) sq[5] = 1.f / fmaxf(sqrtf(v), EPSc);
            } else if (w2 == 2) {
                float v = (l2 < 8) ? hC[l2] : 0.f; v = warp_sum(v);
                if (l2 == 0) sq[4] = 1.f / fmaxf(sqrtf(v), EPSc);
            } else if (w2 == 3) {
                float v = (l2 < 8) ? hD[l2] : 0.f; v = warp_sum(v);
                if (l2 < 16) st_peer(SPA + ((me * 2 + 1) << 2), l2, v);
            }
            BAR4_SYNC();   // wait o1; m2r now free
            {   // W2 row update
                float4* r4 = (float4*)m2r;
                const float4* o24 = (const float4*)o2;
                #pragma unroll
                for (int k = 0; k < 4; k++) {
                    int e4 = t2 + 256 * k;
                    int r = e4 >> 6, j4 = e4 & 63;
                    float sv = LRc * a1f[me * C1 + r];
                    float4 wv = r4[e4], ov = o24[j4];
                    wv.x = q2 * wv.x - sv * ov.x;
                    wv.y = q2 * wv.y - sv * ov.y;
                    wv.z = q2 * wv.z - sv * ov.z;
                    wv.w = q2 * wv.w - sv * ov.w;
                    r4[e4] = wv;
                }
            }
            float ss1 = 0.f;
            {   // W1 update + ss1
                float4* m14 = (float4*)m1;
                const float4* xc4 = (const float4*)xcur;
                #pragma unroll
                for (int k = 0; k < 16; k++) {
                    int e4 = t2 + 256 * k;
                    int c = e4 >> 8, r4i = e4 & 255;
                    float sv = LRc * o1own[c];
                    float4 wv = m14[e4], xv = xc4[r4i];
                    wv.x = q1 * wv.x - sv * xv.x;
                    wv.y = q1 * wv.y - sv * xv.y;
                    wv.z = q1 * wv.z - sv * xv.z;
                    wv.w = q1 * wv.w - sv * xv.w;
                    m14[e4] = wv;
                    ss1 += dot4(wv, wv);
                }
            }
            ss1 = warp_sum(ss1);
            if (l2 == 0) hE[w2] = ss1;
            BAR2();
            if (w2 == 0) {
                float v = (l2 < 8) ? hE[l2] : 0.f; v = warp_sum(v);
                if (l2 < 16) st_peer(SPA + ((me * 2 + 0) << 2), l2, v);
            }
        }
        CLUSTER_SYNC();   // SYNC1 of next step
    }

    // ---- final scales ----
    if (tid < 2) {
        float s = 0.f;
        #pragma unroll
        for (int p = 0; p < NC; p++) s += spart[p * 2 + tid];
        sq[tid] = 1.f / fmaxf(sqrtf(s), EPSc);
    }
    __syncthreads();
    const float q1f = sq[0], q2f = sq[1], q3f = sq[2];

    // ---- write out: W1 | W2 | W3 (row-major), guarded, sanitized ----
    for (int idx = tid; idx < C1 * Dd; idx += T) {
        int c = idx & 15, r = idx >> 4;
        int o = r * Hh + me * C1 + c;
        if (o < out_size) out[o] = sanitize(q1f * m1[c * Dd + r]);
    }
    for (int idx = tid; idx < C1 * Hh; idx += T) {
        int c = idx & 15, i = idx >> 4;
        int o = Dd * Hh + i * Hh + me * C1 + c;
        if (o < out_size) out[o] = sanitize(q2f * m2c[c * Hh + i]);
    }
    for (int idx = tid; idx < 4 * Hh; idx += T) {
        int j = (int)me * 4 + (idx & 3), i = idx >> 2;
        int o = Dd * Hh + Hh * Hh + i * Oo + j;
        if (o < out_size) out[o] = sanitize(q3f * m3[j * Hh + i]);
    }
    for (int o = TOTAL_OUT + (int)me * T + tid; o < out_size; o += NC * T) out[o] = 0.f;
}

extern "C" void kernel_launch(void* const* d_in, const int* in_sizes, int n_in,
                              void* d_out, int out_size) {
    const float* X = 0; const float* Tg = 0;
    const float* W1 = 0; const float* b1 = 0;
    const float* W2 = 0; const float* b2 = 0;
    const float* W3 = 0; const float* b3 = 0;
    for (int i = 0; i < n_in; i++) {
        const float* p = (const float*)d_in[i];
        switch (in_sizes[i]) {
            case 1024 * 1024: X = p; break;
            case 1024 * 256:  W1 = p; break;
            case 256 * 256:   if (!Tg) Tg = p; else W2 = p; break;
            case 256 * 64:    W3 = p; break;
            case 256:         if (!b1) b1 = p; else b2 = p; break;
            case 64:          b3 = p; break;
            default: break;
        }
    }
    cudaFuncSetAttribute(train_kernel, cudaFuncAttributeMaxDynamicSharedMemorySize, SMEM_BYTES);
    cudaFuncSetAttribute(train_kernel, cudaFuncAttributeNonPortableClusterSizeAllowed, 1);

    cudaLaunchConfig_t cfg = {};
    cfg.gridDim = dim3(NC, 1, 1);
    cfg.blockDim = dim3(T, 1, 1);
    cfg.dynamicSmemBytes = SMEM_BYTES;
    cudaLaunchAttribute attrs[1];
    attrs[0].id = cudaLaunchAttributeClusterDimension;
    attrs[0].val.clusterDim.x = NC;
    attrs[0].val.clusterDim.y = 1;
    attrs[0].val.clusterDim.z = 1;
    cfg.attrs = attrs;
    cfg.numAttrs = 1;
    cudaLaunchKernelEx(&cfg, train_kernel, X, Tg, W1, b1, W2, b2, W3, b3,
                       (float*)d_out, out_size);
}

// round 13
// speedup vs baseline: 1.2649x; 1.2649x over previous
#include <cuda_runtime.h>
#include <math.h>
#include <cstdint>

// R9 champion structure (16-CTA cluster, 3 cluster syncs/step, bulk-synchronous)
// widened to T=1024 (32 warps) for 2x latency hiding on the update passes.
// W1/W2 col-sliced, W2 also row-sliced, W3 fully replicated (backward local).
// Activations exchanged via DSMEM pushes; lazy-rescale normalization
// (store unnormalized m, q=1/max(||m||,EPS)); replicated quantities (W3,b2,b3)
// use locally recomputed bit-identical scalars; sliced ones (W1,W2,b1)
// exchange 3 norm partials per step. Spare warps prefetch x/tg in phase A.

#define NC 16
#define T  1024
#define Dd 1024
#define Hh 256
#define Oo 64
#define NSTEPS 1024
#define LRc 0.01f
#define EPSc 1e-8f
#define C1 16
#define TOTAL_OUT (Dd * Hh + Hh * Hh + Hh * Oo)   // 344064

// ---- SMEM layout (float offsets) ----
#define OFF_M1    0        // [C1][Dd] W1 col slice           16384
#define OFF_M2C   16384    // [C1][Hh] W2 col slice            4096
#define OFF_M2R   20480    // [C1][Hh] W2 row slice            4096
#define OFF_M3    24576    // [Oo][Hh] W3 full [j][i]         16384
#define OFF_X     40960    // [2][Dd]                          2048
#define OFF_TG    43008    // [2][Oo]                           128
#define OFF_A1    43136    // [Hh] pushed a1 activations        256
#define OFF_A2    43392    // [Hh] pushed a2 activations        256
#define OFF_A3    43648    // [Oo]                               64
#define OFF_D3    43712    // [Oo]                               64
#define OFF_O2    43776    // [Hh]                              256
#define OFF_O1    44032    // [C1]                               16
#define OFF_MB1   44048    // [C1] b1 slice (unnormalized)       16
#define OFF_MB2   44064    // [Hh] replicated                   256
#define OFF_MB3   44320    // [Oo] replicated                    64
#define OFF_STAGE 44384    // [C1]                               16
#define OFF_SRED  44400    // [32][6]                           192
#define OFF_SQ    44592    // q1,q2,q3,qb1,qb2,qb3                8
#define OFF_SPART 44600    // [NC][3] pushed ss1,ss2,bn1         48
#define SMEM_FLOATS 44648
#define SMEM_BYTES (SMEM_FLOATS * 4)

__device__ __forceinline__ uint32_t smem_u32(const void* p) {
    uint32_t a;
    asm("{ .reg .u64 t; cvta.to.shared.u64 t, %1; cvt.u32.u64 %0, t; }"
        : "=r"(a) : "l"(p));
    return a;
}
__device__ __forceinline__ void st_peer(uint32_t laddr, uint32_t rank, float v) {
    uint32_t r;
    asm volatile("mapa.shared::cluster.u32 %0, %1, %2;" : "=r"(r) : "r"(laddr), "r"(rank));
    asm volatile("st.shared::cluster.f32 [%0], %1;" :: "r"(r), "f"(v) : "memory");
}
#define CLUSTER_SYNC() do { \
    asm volatile("barrier.cluster.arrive.aligned;" ::: "memory"); \
    asm volatile("barrier.cluster.wait.aligned;" ::: "memory");   \
} while (0)

__device__ __forceinline__ float warp_sum(float v) {
    #pragma unroll
    for (int o = 16; o; o >>= 1) v += __shfl_xor_sync(0xffffffffu, v, o);
    return v;
}
__device__ __forceinline__ float sigmoidf(float p) { return 1.f / (1.f + expf(-p)); }
__device__ __forceinline__ float sanitize(float v) { return isfinite(v) ? v : 0.f; }
__device__ __forceinline__ float dot4(float4 a, float4 b) {
    return a.x * b.x + a.y * b.y + a.z * b.z + a.w * b.w;
}

__global__ void __launch_bounds__(T, 1)
train_kernel(const float* __restrict__ X, const float* __restrict__ Tg,
             const float* __restrict__ W1g, const float* __restrict__ b1g,
             const float* __restrict__ W2g, const float* __restrict__ b2g,
             const float* __restrict__ W3g, const float* __restrict__ b3g,
             float* __restrict__ out, int out_size)
{
    extern __shared__ float sm[];
    float* m1    = sm + OFF_M1;
    float* m2c   = sm + OFF_M2C;
    float* m2r   = sm + OFF_M2R;
    float* m3    = sm + OFF_M3;
    float* xb    = sm + OFF_X;
    float* tgb   = sm + OFF_TG;
    float* a1buf = sm + OFF_A1;
    float* a2buf = sm + OFF_A2;
    float* a3buf = sm + OFF_A3;
    float* d3    = sm + OFF_D3;
    float* o2    = sm + OFF_O2;
    float* o1s   = sm + OFF_O1;
    float* mb1   = sm + OFF_MB1;
    float* mb2   = sm + OFF_MB2;
    float* mb3   = sm + OFF_MB3;
    float* stage = sm + OFF_STAGE;
    float* sred  = sm + OFF_SRED;
    float* sq    = sm + OFF_SQ;
    float* spart = sm + OFF_SPART;

    const int tid = threadIdx.x;
    const int w = tid >> 5, lane = tid & 31;

    uint32_t me;
    asm("mov.u32 %0, %%cluster_ctarank;" : "=r"(me));
    const uint32_t sbase = smem_u32(sm);
    const uint32_t A1A = sbase + OFF_A1 * 4;
    const uint32_t A2A = sbase + OFF_A2 * 4;
    const uint32_t SPA = sbase + OFF_SPART * 4;

    // ================= init =================
    for (int idx = tid; idx < C1 * Dd; idx += T) {
        int c = idx & 15, r = idx >> 4;
        m1[c * Dd + r] = W1g[r * Hh + me * C1 + c];
    }
    for (int idx = tid; idx < C1 * Hh; idx += T) {
        int c = idx & 15, i = idx >> 4;
        m2c[c * Hh + i] = W2g[i * Hh + me * C1 + c];
    }
    for (int idx = tid; idx < C1 * Hh; idx += T) {
        int r = idx >> 8, j = idx & 255;
        m2r[r * Hh + j] = W2g[(me * C1 + r) * Hh + j];
    }
    for (int idx = tid; idx < Oo * Hh; idx += T)
        m3[idx] = W3g[(idx & 255) * Oo + (idx >> 8)];
    if (tid < C1) mb1[tid] = b1g[me * C1 + tid];
    if (tid < Hh) mb2[tid] = b2g[tid];
    if (tid < Oo) mb3[tid] = b3g[tid];
    if (tid < 6)  sq[tid] = 1.f;
    if (tid < 48) spart[tid] = 0.f;
    if (tid < 256) ((float4*)xb)[tid] = ((const float4*)X)[tid];
    else if (tid < 320) tgb[tid - 256] = Tg[tid - 256];
    __syncthreads();

    for (int step = 0; step < NSTEPS; ++step) {
        const int par = step & 1;
        const float* xcur = xb + par * Dd;
        float* xnext = xb + (par ^ 1) * Dd;

        // ---- global scalars from pushed partials ----
        if (step > 0 && tid < 3) {
            float s = 0.f;
            #pragma unroll
            for (int p = 0; p < NC; p++) s += spart[p * 3 + tid];
            float qq = 1.f / fmaxf(sqrtf(s), EPSc);
            sq[tid == 0 ? 0 : (tid == 1 ? 1 : 3)] = qq;
        }
        __syncthreads();
        const float q1 = sq[0], q2 = sq[1], q3 = sq[2];
        const float qb1 = sq[3], qb2 = sq[4], qb3 = sq[5];
        const float4* x4 = (const float4*)xcur;

        // ======== Phase A: fwd layer 1 (warps 0-15) | prefetch (16-31) ====
        if (w < 16) {
            const float4* c4 = (const float4*)(m1 + w * Dd);
            float acc = 0.f;
            #pragma unroll
            for (int k = 0; k < 8; k++)
                acc += dot4(c4[k * 32 + lane], x4[k * 32 + lane]);
            acc = warp_sum(acc);
            if (lane == 0) stage[w] = sigmoidf(q1 * acc + qb1 * mb1[w]);
        } else if (step + 1 < NSTEPS) {
            int t2 = tid - 512;
            if (t2 < 256)
                ((float4*)xnext)[t2] = ((const float4*)(X + (step + 1) * Dd))[t2];
            else if (t2 < 320)
                tgb[(par ^ 1) * Oo + (t2 - 256)] = Tg[(step + 1) * Oo + (t2 - 256)];
        }
        __syncthreads();
        if (tid < 256) {
            int j = tid >> 4, p = tid & 15;
            st_peer(A1A + ((me * C1 + j) << 2), p, stage[j]);
        }
        CLUSTER_SYNC();

        // ======== Phase B: fwd layer 2 (warps 0-15) ========
        if (w < 16) {
            const float4* a14 = (const float4*)a1buf;
            const float4* c4 = (const float4*)(m2c + w * Hh);
            float acc = 0.f;
            #pragma unroll
            for (int k = 0; k < 2; k++)
                acc += dot4(c4[k * 32 + lane], a14[k * 32 + lane]);
            acc = warp_sum(acc);
            if (lane == 0) stage[w] = sigmoidf(q2 * acc + qb2 * mb2[me * C1 + w]);
        }
        __syncthreads();
        if (tid < 256) {
            int j = tid >> 4, p = tid & 15;
            st_peer(A2A + ((me * C1 + j) << 2), p, stage[j]);
        }
        CLUSTER_SYNC();

        // ================ local region ================
        // (i) a3: warp w handles j = w, w+32
        {
            const float4* a24 = (const float4*)a2buf;
            const float4* rA = (const float4*)(m3 + w * Hh);
            const float4* rB = (const float4*)(m3 + (w + 32) * Hh);
            float aA = 0.f, aB = 0.f;
            #pragma unroll
            for (int k = 0; k < 2; k++) {
                float4 av = a24[k * 32 + lane];
                aA += dot4(rA[k * 32 + lane], av);
                aB += dot4(rB[k * 32 + lane], av);
            }
            aA = warp_sum(aA); aB = warp_sum(aB);
            if (lane == 0) {
                a3buf[w]      = sigmoidf(q3 * aA + qb3 * mb3[w]);
                a3buf[w + 32] = sigmoidf(q3 * aB + qb3 * mb3[w + 32]);
            }
        }
        __syncthreads();

        // (ii) softmax + d3 (warp 0)
        if (w == 0) {
            const float* tgc = tgb + par * Oo;
            float a30 = a3buf[lane], a31 = a3buf[lane + 32];
            float t0 = tgc[lane], t1 = tgc[lane + 32];
            float m = fmaxf(-a30, -a31);
            #pragma unroll
            for (int o = 16; o; o >>= 1) m = fmaxf(m, __shfl_xor_sync(0xffffffffu, m, o));
            float e0 = expf(-a30 - m), e1 = expf(-a31 - m);
            float s = warp_sum(e0 + e1);
            float inv = 1.f / s;
            d3[lane]      = (t0 - e0 * inv) * a30 * (1.f - a30);
            d3[lane + 32] = (t1 - e1 * inv) * a31 * (1.f - a31);
        }
        __syncthreads();

        // (iii) o2 (pre-update m3)
        if (tid < Hh) {
            const float* col = m3 + tid;
            float r0 = 0.f, r1 = 0.f, r2 = 0.f, r3 = 0.f;
            #pragma unroll
            for (int j = 0; j < Oo; j += 4) {
                r0 += col[(j + 0) * Hh] * d3[j + 0];
                r1 += col[(j + 1) * Hh] * d3[j + 1];
                r2 += col[(j + 2) * Hh] * d3[j + 2];
                r3 += col[(j + 3) * Hh] * d3[j + 3];
            }
            float raw = (r0 + r1) + (r2 + r3);
            float a = a2buf[tid];
            o2[tid] = q3 * raw * a * (1.f - a);
        }
        __syncthreads();

        // (iv) o1 slice (pre-update m2r) + b1 slice update (warps 0-15)
        if (w < 16) {
            const float4* o24 = (const float4*)o2;
            const float4* r4 = (const float4*)(m2r + w * Hh);
            float acc = 0.f;
            #pragma unroll
            for (int k = 0; k < 2; k++)
                acc += dot4(r4[k * 32 + lane], o24[k * 32 + lane]);
            acc = warp_sum(acc);
            if (lane == 0) {
                float a = a1buf[me * C1 + w];
                float ov = q2 * acc * a * (1.f - a);
                o1s[w] = ov;
                mb1[w] = qb1 * mb1[w] - LRc * ov;
            }
        }
        __syncthreads();

        // (v) all weight/bias updates + fused norms (all 32 warps)
        float ss1 = 0.f, ss2 = 0.f, ss3 = 0.f, bn1 = 0.f, bn2 = 0.f, bn3 = 0.f;
        {   // W3 full: 4096 float4, 4 iters
            float4* m34 = (float4*)m3;
            const float4* a24 = (const float4*)a2buf;
            #pragma unroll
            for (int k = 0; k < 4; k++) {
                int e4 = tid + 1024 * k;
                int j = e4 >> 6, i4 = e4 & 63;
                float sv = LRc * d3[j];
                float4 wv = m34[e4], av = a24[i4];
                wv.x = q3 * wv.x - sv * av.x;
                wv.y = q3 * wv.y - sv * av.y;
                wv.z = q3 * wv.z - sv * av.z;
                wv.w = q3 * wv.w - sv * av.w;
                m34[e4] = wv;
                ss3 += dot4(wv, wv);
            }
        }
        {   // W2 col slice: 1024 float4, 1 iter
            float4* c4 = (float4*)m2c;
            const float4* a14 = (const float4*)a1buf;
            int c = tid >> 6, i4 = tid & 63;
            float sv = LRc * o2[me * C1 + c];
            float4 wv = c4[tid], av = a14[i4];
            wv.x = q2 * wv.x - sv * av.x;
            wv.y = q2 * wv.y - sv * av.y;
            wv.z = q2 * wv.z - sv * av.z;
            wv.w = q2 * wv.w - sv * av.w;
            c4[tid] = wv;
            ss2 += dot4(wv, wv);
        }
        {   // W2 row slice: 1024 float4, 1 iter
            float4* r4 = (float4*)m2r;
            const float4* o24 = (const float4*)o2;
            int r = tid >> 6, j4 = tid & 63;
            float sv = LRc * a1buf[me * C1 + r];
            float4 wv = r4[tid], ov = o24[j4];
            wv.x = q2 * wv.x - sv * ov.x;
            wv.y = q2 * wv.y - sv * ov.y;
            wv.z = q2 * wv.z - sv * ov.z;
            wv.w = q2 * wv.w - sv * ov.w;
            r4[tid] = wv;
        }
        {   // W1 slice: 4096 float4, 4 iters
            float4* m14 = (float4*)m1;
            #pragma unroll
            for (int k = 0; k < 4; k++) {
                int e4 = tid + 1024 * k;
                int c = e4 >> 8, r4i = e4 & 255;
                float sv = LRc * o1s[c];
                float4 wv = m14[e4], xv = x4[r4i];
                wv.x = q1 * wv.x - sv * xv.x;
                wv.y = q1 * wv.y - sv * xv.y;
                wv.z = q1 * wv.z - sv * xv.z;
                wv.w = q1 * wv.w - sv * xv.w;
                m14[e4] = wv;
                ss1 += dot4(wv, wv);
            }
        }
        if (tid < Hh) {   // b2 (replicated)
            float v = qb2 * mb2[tid] - LRc * o2[tid];
            mb2[tid] = v; bn2 = v * v;
        }
        if (tid < Oo) {   // b3 (replicated)
            float v = qb3 * mb3[tid] - LRc * d3[tid];
            mb3[tid] = v; bn3 = v * v;
        }
        if (tid < C1) { float v = mb1[tid]; bn1 = v * v; }   // b1 slice (updated)

        // fused 6-way block reduce
        {
            float vals[6] = {ss1, ss2, ss3, bn1, bn2, bn3};
            #pragma unroll
            for (int o = 16; o; o >>= 1) {
                #pragma unroll
                for (int s = 0; s < 6; s++)
                    vals[s] += __shfl_xor_sync(0xffffffffu, vals[s], o);
            }
            if (lane == 0) {
                #pragma unroll
                for (int s = 0; s < 6; s++) sred[w * 6 + s] = vals[s];
            }
        }
        __syncthreads();
        if (w < 6) {
            float v = sred[lane * 6 + w];
            v = warp_sum(v);
            // w: 0=ss1 -> spart slot0, 1=ss2 -> slot1, 2=ss3 -> sq[2],
            //    3=bn1 -> slot2, 4=bn2 -> sq[4], 5=bn3 -> sq[5]
            if (w == 2) { if (lane == 0) sq[2] = 1.f / fmaxf(sqrtf(v), EPSc); }
            else if (w == 4) { if (lane == 0) sq[4] = 1.f / fmaxf(sqrtf(v), EPSc); }
            else if (w == 5) { if (lane == 0) sq[5] = 1.f / fmaxf(sqrtf(v), EPSc); }
            else {
                int slot = (w == 0) ? 0 : ((w == 1) ? 1 : 2);
                if (lane < 16) st_peer(SPA + ((me * 3 + slot) << 2), lane, v);
            }
        }
        CLUSTER_SYNC();
    }

    // ---- final scales ----
    if (tid < 2) {
        float s = 0.f;
        #pragma unroll
        for (int p = 0; p < NC; p++) s += spart[p * 3 + tid];
        sq[tid] = 1.f / fmaxf(sqrtf(s), EPSc);
    }
    __syncthreads();
    const float q1f = sq[0], q2f = sq[1], q3f = sq[2];

    // ---- write out: W1 | W2 | W3 (row-major), guarded, sanitized ----
    for (int idx = tid; idx < C1 * Dd; idx += T) {
        int c = idx & 15, r = idx >> 4;
        int o = r * Hh + me * C1 + c;
        if (o < out_size) out[o] = sanitize(q1f * m1[c * Dd + r]);
    }
    for (int idx = tid; idx < C1 * Hh; idx += T) {
        int c = idx & 15, i = idx >> 4;
        int o = Dd * Hh + i * Hh + me * C1 + c;
        if (o < out_size) out[o] = sanitize(q2f * m2c[c * Hh + i]);
    }
    for (int idx = tid; idx < 4 * Hh; idx += T) {
        int j = (int)me * 4 + (idx & 3), i = idx >> 2;
        int o = Dd * Hh + Hh * Hh + i * Oo + j;
        if (o < out_size) out[o] = sanitize(q3f * m3[j * Hh + i]);
    }
    for (int o = TOTAL_OUT + (int)me * T + tid; o < out_size; o += NC * T) out[o] = 0.f;
}

extern "C" void kernel_launch(void* const* d_in, const int* in_sizes, int n_in,
                              void* d_out, int out_size) {
    const float* X = 0; const float* Tg = 0;
    const float* W1 = 0; const float* b1 = 0;
    const float* W2 = 0; const float* b2 = 0;
    const float* W3 = 0; const float* b3 = 0;
    for (int i = 0; i < n_in; i++) {
        const float* p = (const float*)d_in[i];
        switch (in_sizes[i]) {
            case 1024 * 1024: X = p; break;
            case 1024 * 256:  W1 = p; break;
            case 256 * 256:   if (!Tg) Tg = p; else W2 = p; break;
            case 256 * 64:    W3 = p; break;
            case 256:         if (!b1) b1 = p; else b2 = p; break;
            case 64:          b3 = p; break;
            default: break;
        }
    }
    cudaFuncSetAttribute(train_kernel, cudaFuncAttributeMaxDynamicSharedMemorySize, SMEM_BYTES);
    cudaFuncSetAttribute(train_kernel, cudaFuncAttributeNonPortableClusterSizeAllowed, 1);

    cudaLaunchConfig_t cfg = {};
    cfg.gridDim = dim3(NC, 1, 1);
    cfg.blockDim = dim3(T, 1, 1);
    cfg.dynamicSmemBytes = SMEM_BYTES;
    cudaLaunchAttribute attrs[1];
    attrs[0].id = cudaLaunchAttributeClusterDimension;
    attrs[0].val.clusterDim.x = NC;
    attrs[0].val.clusterDim.y = 1;
    attrs[0].val.clusterDim.z = 1;
    cfg.attrs = attrs;
    cfg.numAttrs = 1;
    cudaLaunchKernelEx(&cfg, train_kernel, X, Tg, W1, b1, W2, b2, W3, b3,
                       (float*)d_out, out_size);
}

// round 15
// speedup vs baseline: 1.3433x; 1.0620x over previous
#include <cuda_runtime.h>
#include <math.h>
#include <cstdint>

// 16-CTA cluster, persistent, bulk-synchronous, TWO cluster syncs per step.
// W1/W2 col-sliced, W2 also row-sliced, W3 replicated. RAW preactivations
// exchanged (replicated), sigmoids computed replicated. All Frobenius norms
// via exact closed-form recurrences from local dots:
//   ||q*m - LR*a*o^T||^2 = q^2*S - 2*LR*q*dot(o,acc_raw) + LR^2*||a||^2*||o||^2
// -> no norm accumulation in update passes, no norm exchange. End-of-step
// sync carries o1 slices + next-step raw acc1; W3/W2 updates hide inside the
// arrive/wait window of that sync. (R15: fixed pragma-on-brace-line compile error.)

#define NC 16
#define T  512
#define Dd 1024
#define Hh 256
#define Oo 64
#define NSTEPS 1024
#define LRc 0.01f
#define EPSc 1e-8f
#define C1 16
#define TOTAL_OUT (Dd * Hh + Hh * Hh + Hh * Oo)   // 344064

// ---- SMEM layout (float offsets) ----
#define OFF_M1    0        // [C1][Dd]                         16384
#define OFF_M2C   16384    // [C1][Hh]                          4096
#define OFF_M2R   20480    // [C1][Hh]                          4096
#define OFF_M3    24576    // [Oo][Hh]                         16384
#define OFF_X     40960    // [2][Dd]                           2048
#define OFF_TG    43008    // [2][Oo]                            128
#define OFF_ACC1  43136    // [2][Hh] pushed raw l1 preacts      512
#define OFF_ACC2  43648    // [Hh] pushed raw l2 preacts         256
#define OFF_O1F   43904    // [Hh] pushed o1 full                256
#define OFF_A1F   44160    // [Hh]                               256
#define OFF_A2C   44416    // [Hh]                               256
#define OFF_A3R   44672    // [Oo] raw l3 preacts                 64
#define OFF_D3    44736    // [Oo]                                64
#define OFF_O2    44800    // [Hh]                               256
#define OFF_O1OWN 45056    // [C1]                                16
#define OFF_MB1   45072    // [Hh] replicated                    256
#define OFF_MB2   45328    // [Hh]                               256
#define OFF_MB3   45584    // [Oo]                                64
#define OFF_STG   45648    // [C1]                                16
#define OFF_SRED  45664    // [16][9]                            144
#define OFF_SRES  45808    // [9]                                  9
#define OFF_SQ    45817    // q1,q2,q3,qb1,qb2,qb3                 6
#define OFF_SS    45823    // S1,S2,S3,BN1,BN2,BN3                 6
#define OFF_SNX   45829    // ||x||^2 parity pair                  2
#define OFF_SPART 45832    // [NC][2] init-only pushed S1,S2 par  32
#define SMEM_FLOATS 45864
#define SMEM_BYTES (SMEM_FLOATS * 4)

__device__ __forceinline__ uint32_t smem_u32(const void* p) {
    uint32_t a;
    asm("{ .reg .u64 t; cvta.to.shared.u64 t, %1; cvt.u32.u64 %0, t; }"
        : "=r"(a) : "l"(p));
    return a;
}
__device__ __forceinline__ void st_peer(uint32_t laddr, uint32_t rank, float v) {
    uint32_t r;
    asm volatile("mapa.shared::cluster.u32 %0, %1, %2;" : "=r"(r) : "r"(laddr), "r"(rank));
    asm volatile("st.shared::cluster.f32 [%0], %1;" :: "r"(r), "f"(v) : "memory");
}
#define CLUSTER_SYNC() do { \
    asm volatile("barrier.cluster.arrive.aligned;" ::: "memory"); \
    asm volatile("barrier.cluster.wait.aligned;" ::: "memory");   \
} while (0)
#define CLUSTER_ARRIVE() asm volatile("barrier.cluster.arrive.aligned;" ::: "memory")
#define CLUSTER_WAIT()   asm volatile("barrier.cluster.wait.aligned;" ::: "memory")

__device__ __forceinline__ float warp_sum(float v) {
    #pragma unroll
    for (int o = 16; o; o >>= 1) v += __shfl_xor_sync(0xffffffffu, v, o);
    return v;
}
__device__ __forceinline__ float sigmoidf(float p) { return 1.f / (1.f + expf(-p)); }
__device__ __forceinline__ float sanitize(float v) { return isfinite(v) ? v : 0.f; }
__device__ __forceinline__ float dot4(float4 a, float4 b) {
    return a.x * b.x + a.y * b.y + a.z * b.z + a.w * b.w;
}

__global__ void __launch_bounds__(T, 1)
train_kernel(const float* __restrict__ X, const float* __restrict__ Tg,
             const float* __restrict__ W1g, const float* __restrict__ b1g,
             const float* __restrict__ W2g, const float* __restrict__ b2g,
             const float* __restrict__ W3g, const float* __restrict__ b3g,
             float* __restrict__ out, int out_size)
{
    extern __shared__ float sm[];
    float* m1   = sm + OFF_M1;
    float* m2c  = sm + OFF_M2C;
    float* m2r  = sm + OFF_M2R;
    float* m3   = sm + OFF_M3;
    float* xb   = sm + OFF_X;
    float* tgb  = sm + OFF_TG;
    float* acc1 = sm + OFF_ACC1;
    float* acc2r= sm + OFF_ACC2;
    float* o1f  = sm + OFF_O1F;
    float* a1f  = sm + OFF_A1F;
    float* a2c  = sm + OFF_A2C;
    float* a3r  = sm + OFF_A3R;
    float* d3   = sm + OFF_D3;
    float* o2   = sm + OFF_O2;
    float* o1own= sm + OFF_O1OWN;
    float* mb1  = sm + OFF_MB1;
    float* mb2  = sm + OFF_MB2;
    float* mb3  = sm + OFF_MB3;
    float* stg  = sm + OFF_STG;
    float* sred = sm + OFF_SRED;
    float* sres = sm + OFF_SRES;
    float* sq   = sm + OFF_SQ;
    float* sS   = sm + OFF_SS;
    float* snx  = sm + OFF_SNX;
    float* spart= sm + OFF_SPART;

    const int tid = threadIdx.x;
    const int w = tid >> 5, lane = tid & 31;

    uint32_t me;
    asm("mov.u32 %0, %%cluster_ctarank;" : "=r"(me));
    const uint32_t sbase = smem_u32(sm);
    const uint32_t ACC1A = sbase + OFF_ACC1 * 4;
    const uint32_t ACC2A = sbase + OFF_ACC2 * 4;
    const uint32_t O1FA  = sbase + OFF_O1F * 4;
    const uint32_t SPA   = sbase + OFF_SPART * 4;

    // ================= init =================
    for (int idx = tid; idx < C1 * Dd; idx += T) {
        int c = idx & 15, r = idx >> 4;
        m1[c * Dd + r] = W1g[r * Hh + me * C1 + c];
    }
    for (int idx = tid; idx < C1 * Hh; idx += T) {
        int c = idx & 15, i = idx >> 4;
        m2c[c * Hh + i] = W2g[i * Hh + me * C1 + c];
    }
    for (int idx = tid; idx < C1 * Hh; idx += T) {
        int r = idx >> 8, j = idx & 255;
        m2r[r * Hh + j] = W2g[(me * C1 + r) * Hh + j];
    }
    for (int idx = tid; idx < Oo * Hh; idx += T)
        m3[idx] = W3g[(idx & 255) * Oo + (idx >> 8)];
    if (tid < Hh) { mb1[tid] = b1g[tid]; mb2[tid] = b2g[tid]; o1f[tid] = 0.f; }
    if (tid < Oo) mb3[tid] = b3g[tid];
    if (tid < 6)  sq[tid] = 1.f;
    if (tid < 256) ((float4*)xb)[tid] = ((const float4*)X)[tid];
    else if (tid < 320) tgb[tid - 256] = Tg[tid - 256];
    __syncthreads();

    // ---- initial norm partials (7-way fused reduce) ----
    {
        float p1 = 0.f, p2 = 0.f, p3 = 0.f, pb1 = 0.f, pb2 = 0.f, pb3 = 0.f, px = 0.f;
        for (int idx = tid; idx < C1 * Dd; idx += T) { float v = m1[idx]; p1 += v * v; }
        for (int idx = tid; idx < C1 * Hh; idx += T) { float v = m2c[idx]; p2 += v * v; }
        for (int idx = tid; idx < Oo * Hh; idx += T) { float v = m3[idx]; p3 += v * v; }
        if (tid < Hh) { float a = mb1[tid], b = mb2[tid]; pb1 = a * a; pb2 = b * b; }
        if (tid < Oo) { float c = mb3[tid]; pb3 = c * c; }
        for (int i = tid; i < Dd; i += T) { float v = xb[i]; px += v * v; }
        float vals[7] = {p1, p2, p3, pb1, pb2, pb3, px};
        #pragma unroll
        for (int s = 0; s < 7; s++) vals[s] = warp_sum(vals[s]);
        if (lane == 0) {
            #pragma unroll
            for (int s = 0; s < 7; s++) sred[w * 9 + s] = vals[s];
        }
        __syncthreads();
        if (w < 7) {
            float v = (lane < 16) ? sred[lane * 9 + w] : 0.f;
            v = warp_sum(v);
            if (lane == 0) sres[w] = v;
        }
        __syncthreads();
        if (tid == 0) {
            sS[2] = sres[2]; sS[3] = sres[3]; sS[4] = sres[4]; sS[5] = sres[5];
            snx[0] = sres[6]; snx[1] = 0.f;
        }
    }
    // ---- prologue acc1(0) MV ----
    if (w < 16) {
        const float4* c4 = (const float4*)(m1 + w * Dd);
        const float4* x4 = (const float4*)xb;
        float acc = 0.f;
        #pragma unroll
        for (int k = 0; k < 8; k++) acc += dot4(c4[k * 32 + lane], x4[k * 32 + lane]);
        acc = warp_sum(acc);
        if (lane == 0) stg[w] = acc;
    }
    __syncthreads();
    CLUSTER_SYNC();   // all CTAs initialized before pushes
    if (tid < 256) st_peer(ACC1A + ((me * C1 + (tid >> 4)) << 2), tid & 15, stg[tid >> 4]);
    if (tid < 32) {   // push initial S1,S2 partials
        int k = tid >> 4, p = tid & 15;
        st_peer(SPA + ((me * 2 + k) << 2), p, sres[k]);
    }
    CLUSTER_ARRIVE();

    for (int step = 0; step < NSTEPS; ++step) {
        CLUSTER_WAIT();   // S_a: acc1r(step) + o1f(step-1) delivered
        const int par = step & 1;
        const float* xcur = xb + par * Dd;
        float* xnext = xb + (par ^ 1) * Dd;
        const float* acc1c = acc1 + par * Hh;
        const float* acc1p = acc1 + (par ^ 1) * Hh;

        // ---- item 1: layer-1 scalars (closed-form) ----
        const float q1o = sq[0], qb1o = sq[3];
        {
            float v0 = 0.f, v1 = 0.f, v2 = 0.f;
            if (tid < Hh) {
                float ov = o1f[tid];
                v0 = ov * acc1p[tid]; v1 = mb1[tid] * ov; v2 = ov * ov;
            }
            v0 = warp_sum(v0); v1 = warp_sum(v1); v2 = warp_sum(v2);
            if (lane == 0) { sred[w * 9] = v0; sred[w * 9 + 1] = v1; sred[w * 9 + 2] = v2; }
            __syncthreads();
            if (w < 3) {
                float v = (lane < 16) ? sred[lane * 9 + w] : 0.f;
                v = warp_sum(v);
                if (lane == 0) sres[w] = v;
            }
            __syncthreads();
            if (tid == 0) {
                if (step == 0) {
                    float s1 = 0.f, s2 = 0.f;
                    #pragma unroll
                    for (int p = 0; p < NC; p++) { s1 += spart[p * 2]; s2 += spart[p * 2 + 1]; }
                    sS[0] = s1; sS[1] = s2;
                } else {
                    float r1 = sres[0], r2 = sres[1], r3 = sres[2];
                    float S1 = q1o * q1o * sS[0] - 2.f * LRc * q1o * r1
                             + LRc * LRc * snx[par ^ 1] * r3;
                    sS[0] = S1; sq[0] = 1.f / fmaxf(sqrtf(S1), EPSc);
                    float B1 = qb1o * qb1o * sS[3] - 2.f * LRc * qb1o * r2 + LRc * LRc * r3;
                    sS[3] = B1; sq[3] = 1.f / fmaxf(sqrtf(B1), EPSc);
                }
            }
            __syncthreads();
        }
        const float q1n = sq[0], qb1n = sq[3];

        // ---- item 2: b1 update + a1 (replicated) ----
        if (tid < Hh) {
            float v = qb1o * mb1[tid] - LRc * o1f[tid];
            mb1[tid] = v;
            a1f[tid] = sigmoidf(q1n * acc1c[tid] + qb1n * v);
        }
        __syncthreads();

        // ---- item 3: acc2 MV (raw), push, arrive ----
        if (w < 16) {
            const float4* a14 = (const float4*)a1f;
            const float4* c4 = (const float4*)(m2c + w * Hh);
            float acc = 0.f;
            #pragma unroll
            for (int k = 0; k < 2; k++) acc += dot4(c4[k * 32 + lane], a14[k * 32 + lane]);
            acc = warp_sum(acc);
            if (lane == 0) stg[w] = acc;
        }
        __syncthreads();
        if (tid < 256) st_peer(ACC2A + ((me * C1 + (tid >> 4)) << 2), tid & 15, stg[tid >> 4]);
        CLUSTER_ARRIVE();

        // ---- item 4: prefetch (hides S_b latency) ----
        if (step + 1 < NSTEPS) {
            if (tid < 256)
                ((float4*)xnext)[tid] = ((const float4*)(X + (step + 1) * Dd))[tid];
            else if (tid < 320)
                tgb[(par ^ 1) * Oo + (tid - 256)] = Tg[(step + 1) * Oo + (tid - 256)];
        }
        CLUSTER_WAIT();   // S_b

        // ---- item 5: a2 (replicated) ----
        const float q2o = sq[1], qb2o = sq[4], q3o = sq[2], qb3o = sq[5];
        if (tid < Hh) a2c[tid] = sigmoidf(q2o * acc2r[tid] + qb2o * mb2[tid]);
        __syncthreads();

        // ---- item 6: a3 raw MV (warps 0-15, 4 rows each) ----
        if (w < 16) {
            const float4* a24 = (const float4*)a2c;
            float acc[4] = {0.f, 0.f, 0.f, 0.f};
            #pragma unroll
            for (int s = 0; s < 4; s++) {
                const float4* r4 = (const float4*)(m3 + (w + 16 * s) * Hh);
                #pragma unroll
                for (int k = 0; k < 2; k++)
                    acc[s] += dot4(r4[k * 32 + lane], a24[k * 32 + lane]);
            }
            #pragma unroll
            for (int o = 16; o; o >>= 1) {
                #pragma unroll
                for (int s = 0; s < 4; s++)
                    acc[s] += __shfl_xor_sync(0xffffffffu, acc[s], o);
            }
            if (lane == 0) {
                #pragma unroll
                for (int s = 0; s < 4; s++) a3r[w + 16 * s] = acc[s];
            }
        }
        __syncthreads();

        // ---- item 7: sigmoid + softmax + d3 (warp 0) ----
        if (w == 0) {
            float a30 = sigmoidf(q3o * a3r[lane] + qb3o * mb3[lane]);
            float a31 = sigmoidf(q3o * a3r[lane + 32] + qb3o * mb3[lane + 32]);
            const float* tgc = tgb + par * Oo;
            float t0 = tgc[lane], t1 = tgc[lane + 32];
            float m = fmaxf(-a30, -a31);
            #pragma unroll
            for (int o = 16; o; o >>= 1) m = fmaxf(m, __shfl_xor_sync(0xffffffffu, m, o));
            float e0 = expf(-a30 - m), e1 = expf(-a31 - m);
            float s = warp_sum(e0 + e1);
            float inv = 1.f / s;
            d3[lane]      = (t0 - e0 * inv) * a30 * (1.f - a30);
            d3[lane + 32] = (t1 - e1 * inv) * a31 * (1.f - a31);
        }
        __syncthreads();

        // ---- item 8: o2 (pre-update m3) ----
        if (tid < Hh) {
            const float* col = m3 + tid;
            float r0 = 0.f, r1 = 0.f, r2 = 0.f, r3 = 0.f;
            #pragma unroll
            for (int j = 0; j < Oo; j += 4) {
                r0 += col[(j + 0) * Hh] * d3[j + 0];
                r1 += col[(j + 1) * Hh] * d3[j + 1];
                r2 += col[(j + 2) * Hh] * d3[j + 2];
                r3 += col[(j + 3) * Hh] * d3[j + 3];
            }
            float raw = (r0 + r1) + (r2 + r3);
            float a = a2c[tid];
            o2[tid] = q3o * raw * a * (1.f - a);
        }
        __syncthreads();

        // ---- item 9: o1 own slice (pre-update m2r) ----
        if (w < 16) {
            const float4* o24 = (const float4*)o2;
            const float4* r4 = (const float4*)(m2r + w * Hh);
            float acc = 0.f;
            #pragma unroll
            for (int k = 0; k < 2; k++) acc += dot4(r4[k * 32 + lane], o24[k * 32 + lane]);
            acc = warp_sum(acc);
            if (lane == 0) {
                float a = a1f[me * C1 + w];
                o1own[w] = q2o * acc * a * (1.f - a);
            }
        }
        __syncthreads();

        // ---- item 10: 9-way local reduce -> layer-2/3 scalars + b2/b3 ----
        {
            float u[9];
            #pragma unroll
            for (int s = 0; s < 9; s++) u[s] = 0.f;
            if (tid < Hh) {
                float o2v = o2[tid], a1v = a1f[tid], a2v = a2c[tid];
                u[0] = o2v * acc2r[tid];
                u[1] = o2v * o2v;
                u[2] = mb2[tid] * o2v;
                u[3] = a1v * a1v;
                u[7] = a2v * a2v;
            }
            if (tid < Oo) {
                float dv = d3[tid];
                u[4] = dv * a3r[tid];
                u[5] = dv * dv;
                u[6] = mb3[tid] * dv;
            }
            { float x0 = xnext[tid], x1 = xnext[tid + 512]; u[8] = x0 * x0 + x1 * x1; }
            #pragma unroll
            for (int s = 0; s < 9; s++) u[s] = warp_sum(u[s]);
            if (lane == 0) {
                #pragma unroll
                for (int s = 0; s < 9; s++) sred[w * 9 + s] = u[s];
            }
            __syncthreads();
            if (w < 9) {
                float v = (lane < 16) ? sred[lane * 9 + w] : 0.f;
                v = warp_sum(v);
                if (lane == 0) sres[w] = v;
            }
            __syncthreads();
            if (tid == 0) {
                float S2 = q2o * q2o * sS[1] - 2.f * LRc * q2o * sres[0]
                         + LRc * LRc * sres[3] * sres[1];
                sS[1] = S2; sq[1] = 1.f / fmaxf(sqrtf(S2), EPSc);
                float B2 = qb2o * qb2o * sS[4] - 2.f * LRc * qb2o * sres[2]
                         + LRc * LRc * sres[1];
                sS[4] = B2; sq[4] = 1.f / fmaxf(sqrtf(B2), EPSc);
                float S3 = q3o * q3o * sS[2] - 2.f * LRc * q3o * sres[4]
                         + LRc * LRc * sres[7] * sres[5];
                sS[2] = S3; sq[2] = 1.f / fmaxf(sqrtf(S3), EPSc);
                float B3 = qb3o * qb3o * sS[5] - 2.f * LRc * qb3o * sres[6]
                         + LRc * LRc * sres[5];
                sS[5] = B3; sq[5] = 1.f / fmaxf(sqrtf(B3), EPSc);
                snx[par ^ 1] = sres[8];
            }
            if (tid < Hh) mb2[tid] = qb2o * mb2[tid] - LRc * o2[tid];
            if (tid < Oo) mb3[tid] = qb3o * mb3[tid] - LRc * d3[tid];
            __syncthreads();
        }

        // ---- tail (a): W1 update ----
        {
            float4* m14 = (float4*)m1;
            const float4* xc4 = (const float4*)xcur;
            #pragma unroll
            for (int k = 0; k < 8; k++) {
                int e4 = tid + 512 * k;
                int c = e4 >> 8, r4i = e4 & 255;
                float sv = LRc * o1own[c];
                float4 wv = m14[e4], xv = xc4[r4i];
                wv.x = q1n * wv.x - sv * xv.x;
                wv.y = q1n * wv.y - sv * xv.y;
                wv.z = q1n * wv.z - sv * xv.z;
                wv.w = q1n * wv.w - sv * xv.w;
                m14[e4] = wv;
            }
        }
        __syncthreads();
        // ---- tail (b): acc1(t+1) raw MV on updated m1 ----
        if (w < 16) {
            const float4* c4 = (const float4*)(m1 + w * Dd);
            const float4* xn4 = (const float4*)xnext;
            float acc = 0.f;
            #pragma unroll
            for (int k = 0; k < 8; k++) acc += dot4(c4[k * 32 + lane], xn4[k * 32 + lane]);
            acc = warp_sum(acc);
            if (lane == 0) stg[w] = acc;
        }
        __syncthreads();
        // ---- tail (c): pushes + arrive ----
        if (tid < 256) {
            int j = tid >> 4, p = tid & 15;
            st_peer(ACC1A + ((((par ^ 1) * Hh) + me * C1 + j) << 2), p, stg[j]);
            st_peer(O1FA + ((me * C1 + j) << 2), p, o1own[j]);
        }
        CLUSTER_ARRIVE();
        // ---- tail (d): W3 update (hides S_a) ----
        {
            float4* m34 = (float4*)m3;
            const float4* a24 = (const float4*)a2c;
            #pragma unroll
            for (int k = 0; k < 8; k++) {
                int e4 = tid + 512 * k;
                int j = e4 >> 6, i4 = e4 & 63;
                float sv = LRc * d3[j];
                float4 wv = m34[e4], av = a24[i4];
                wv.x = q3o * wv.x - sv * av.x;
                wv.y = q3o * wv.y - sv * av.y;
                wv.z = q3o * wv.z - sv * av.z;
                wv.w = q3o * wv.w - sv * av.w;
                m34[e4] = wv;
            }
        }
        // ---- tail (e): W2 col update ----
        {
            float4* c4 = (float4*)m2c;
            const float4* a14 = (const float4*)a1f;
            #pragma unroll
            for (int k = 0; k < 2; k++) {
                int e4 = tid + 512 * k;
                int c = e4 >> 6, i4 = e4 & 63;
                float sv = LRc * o2[me * C1 + c];
                float4 wv = c4[e4], av = a14[i4];
                wv.x = q2o * wv.x - sv * av.x;
                wv.y = q2o * wv.y - sv * av.y;
                wv.z = q2o * wv.z - sv * av.z;
                wv.w = q2o * wv.w - sv * av.w;
                c4[e4] = wv;
            }
        }
        // ---- tail (f): W2 row update ----
        {
            float4* r4 = (float4*)m2r;
            const float4* o24 = (const float4*)o2;
            #pragma unroll
            for (int k = 0; k < 2; k++) {
                int e4 = tid + 512 * k;
                int r = e4 >> 6, j4 = e4 & 63;
                float sv = LRc * a1f[me * C1 + r];
                float4 wv = r4[e4], ov = o24[j4];
                wv.x = q2o * wv.x - sv * ov.x;
                wv.y = q2o * wv.y - sv * ov.y;
                wv.z = q2o * wv.z - sv * ov.z;
                wv.w = q2o * wv.w - sv * ov.w;
                r4[e4] = wv;
            }
        }
        __syncthreads();
    }

    CLUSTER_WAIT();   // pair the final arrive; delivers o1f(1023) + acc1r(1023) intact
    // final q1 via closed form (o1f(1023), acc1r in parity-1 buffer, ||x_1023||^2 in snx[1])
    {
        const float q1o = sq[0];
        const float* a1p = acc1 + 1 * Hh;
        float v0 = 0.f, v2 = 0.f;
        if (tid < Hh) { float ov = o1f[tid]; v0 = ov * a1p[tid]; v2 = ov * ov; }
        v0 = warp_sum(v0); v2 = warp_sum(v2);
        if (lane == 0) { sred[w * 9] = v0; sred[w * 9 + 1] = v2; }
        __syncthreads();
        if (w < 2) {
            float v = (lane < 16) ? sred[lane * 9 + w] : 0.f;
            v = warp_sum(v);
            if (lane == 0) sres[w] = v;
        }
        __syncthreads();
        if (tid == 0) {
            float S1 = q1o * q1o * sS[0] - 2.f * LRc * q1o * sres[0]
                     + LRc * LRc * snx[1] * sres[1];
            sq[0] = 1.f / fmaxf(sqrtf(S1), EPSc);
        }
        __syncthreads();
    }
    const float q1f = sq[0], q2f = sq[1], q3f = sq[2];

    // ---- write out: W1 | W2 | W3 (row-major), guarded, sanitized ----
    for (int idx = tid; idx < C1 * Dd; idx += T) {
        int c = idx & 15, r = idx >> 4;
        int o = r * Hh + me * C1 + c;
        if (o < out_size) out[o] = sanitize(q1f * m1[c * Dd + r]);
    }
    for (int idx = tid; idx < C1 * Hh; idx += T) {
        int c = idx & 15, i = idx >> 4;
        int o = Dd * Hh + i * Hh + me * C1 + c;
        if (o < out_size) out[o] = sanitize(q2f * m2c[c * Hh + i]);
    }
    for (int idx = tid; idx < 4 * Hh; idx += T) {
        int j = (int)me * 4 + (idx & 3), i = idx >> 2;
        int o = Dd * Hh + Hh * Hh + i * Oo + j;
        if (o < out_size) out[o] = sanitize(q3f * m3[j * Hh + i]);
    }
    for (int o = TOTAL_OUT + (int)me * T + tid; o < out_size; o += NC * T) out[o] = 0.f;
}

extern "C" void kernel_launch(void* const* d_in, const int* in_sizes, int n_in,
                              void* d_out, int out_size) {
    const float* X = 0; const float* Tg = 0;
    const float* W1 = 0; const float* b1 = 0;
    const float* W2 = 0; const float* b2 = 0;
    const float* W3 = 0; const float* b3 = 0;
    for (int i = 0; i < n_in; i++) {
        const float* p = (const float*)d_in[i];
        switch (in_sizes[i]) {
            case 1024 * 1024: X = p; break;
            case 1024 * 256:  W1 = p; break;
            case 256 * 256:   if (!Tg) Tg = p; else W2 = p; break;
            case 256 * 64:    W3 = p; break;
            case 256:         if (!b1) b1 = p; else b2 = p; break;
            case 64:          b3 = p; break;
            default: break;
        }
    }
    cudaFuncSetAttribute(train_kernel, cudaFuncAttributeMaxDynamicSharedMemorySize, SMEM_BYTES);
    cudaFuncSetAttribute(train_kernel, cudaFuncAttributeNonPortableClusterSizeAllowed, 1);

    cudaLaunchConfig_t cfg = {};
    cfg.gridDim = dim3(NC, 1, 1);
    cfg.blockDim = dim3(T, 1, 1);
    cfg.dynamicSmemBytes = SMEM_BYTES;
    cudaLaunchAttribute attrs[1];
    attrs[0].id = cudaLaunchAttributeClusterDimension;
    attrs[0].val.clusterDim.x = NC;
    attrs[0].val.clusterDim.y = 1;
    attrs[0].val.clusterDim.z = 1;
    cfg.attrs = attrs;
    cfg.numAttrs = 1;
    cudaLaunchKernelEx(&cfg, train_kernel, X, Tg, W1, b1, W2, b2, W3, b3,
                       (float*)d_out, out_size);
}

// round 16
// speedup vs baseline: 1.4834x; 1.1043x over previous
#include <cuda_runtime.h>
#include <math.h>
#include <cstdint>

// 16-CTA cluster, persistent, bulk-synchronous, TWO cluster syncs per step.
// W1/W2 col-sliced, W2 also row-sliced, W3 replicated. RAW preactivations
// exchanged (replicated), sigmoids computed replicated. Norms via exact
// closed-form recurrences from local dots. R16: latency-parallel reductions
// (one warp per scalar, concurrent with o1 MV) and fused W1-update+next-MV
// single pass (warp-per-column).

#define NC 16
#define T  512
#define Dd 1024
#define Hh 256
#define Oo 64
#define NSTEPS 1024
#define LRc 0.01f
#define EPSc 1e-8f
#define C1 16
#define TOTAL_OUT (Dd * Hh + Hh * Hh + Hh * Oo)   // 344064

// ---- SMEM layout (float offsets) ----
#define OFF_M1    0        // [C1][Dd]                         16384
#define OFF_M2C   16384    // [C1][Hh]                          4096
#define OFF_M2R   20480    // [C1][Hh]                          4096
#define OFF_M3    24576    // [Oo][Hh]                         16384
#define OFF_X     40960    // [2][Dd]                           2048
#define OFF_TG    43008    // [2][Oo]                            128
#define OFF_ACC1  43136    // [2][Hh] pushed raw l1 preacts      512
#define OFF_ACC2  43648    // [Hh] pushed raw l2 preacts         256
#define OFF_O1F   43904    // [Hh] pushed o1 full                256
#define OFF_A1F   44160    // [Hh]                               256
#define OFF_A2C   44416    // [Hh]                               256
#define OFF_A3R   44672    // [Oo] raw l3 preacts                 64
#define OFF_D3    44736    // [Oo]                                64
#define OFF_O2    44800    // [Hh]                               256
#define OFF_O1OWN 45056    // [C1]                                16
#define OFF_MB1   45072    // [Hh] replicated                    256
#define OFF_MB2   45328    // [Hh]                               256
#define OFF_MB3   45584    // [Oo]                                64
#define OFF_STG   45648    // [C1]                                16
#define OFF_SRED  45664    // [16][9]                            144
#define OFF_SRES  45808    // [9]                                  9
#define OFF_SQ    45817    // q1,q2,q3,qb1,qb2,qb3                 6
#define OFF_SS    45823    // S1,S2,S3,BN1,BN2,BN3                 6
#define OFF_SNX   45829    // ||x||^2 parity pair                  2
#define OFF_SPART 45832    // [NC][2] init-only pushed S1,S2 par  32
#define SMEM_FLOATS 45864
#define SMEM_BYTES (SMEM_FLOATS * 4)

__device__ __forceinline__ uint32_t smem_u32(const void* p) {
    uint32_t a;
    asm("{ .reg .u64 t; cvta.to.shared.u64 t, %1; cvt.u32.u64 %0, t; }"
        : "=r"(a) : "l"(p));
    return a;
}
__device__ __forceinline__ void st_peer(uint32_t laddr, uint32_t rank, float v) {
    uint32_t r;
    asm volatile("mapa.shared::cluster.u32 %0, %1, %2;" : "=r"(r) : "r"(laddr), "r"(rank));
    asm volatile("st.shared::cluster.f32 [%0], %1;" :: "r"(r), "f"(v) : "memory");
}
#define CLUSTER_SYNC() do { \
    asm volatile("barrier.cluster.arrive.aligned;" ::: "memory"); \
    asm volatile("barrier.cluster.wait.aligned;" ::: "memory");   \
} while (0)
#define CLUSTER_ARRIVE() asm volatile("barrier.cluster.arrive.aligned;" ::: "memory")
#define CLUSTER_WAIT()   asm volatile("barrier.cluster.wait.aligned;" ::: "memory")

__device__ __forceinline__ float warp_sum(float v) {
    #pragma unroll
    for (int o = 16; o; o >>= 1) v += __shfl_xor_sync(0xffffffffu, v, o);
    return v;
}
__device__ __forceinline__ float sigmoidf(float p) { return 1.f / (1.f + expf(-p)); }
__device__ __forceinline__ float sanitize(float v) { return isfinite(v) ? v : 0.f; }
__device__ __forceinline__ float dot4(float4 a, float4 b) {
    return a.x * b.x + a.y * b.y + a.z * b.z + a.w * b.w;
}

__global__ void __launch_bounds__(T, 1)
train_kernel(const float* __restrict__ X, const float* __restrict__ Tg,
             const float* __restrict__ W1g, const float* __restrict__ b1g,
             const float* __restrict__ W2g, const float* __restrict__ b2g,
             const float* __restrict__ W3g, const float* __restrict__ b3g,
             float* __restrict__ out, int out_size)
{
    extern __shared__ float sm[];
    float* m1   = sm + OFF_M1;
    float* m2c  = sm + OFF_M2C;
    float* m2r  = sm + OFF_M2R;
    float* m3   = sm + OFF_M3;
    float* xb   = sm + OFF_X;
    float* tgb  = sm + OFF_TG;
    float* acc1 = sm + OFF_ACC1;
    float* acc2r= sm + OFF_ACC2;
    float* o1f  = sm + OFF_O1F;
    float* a1f  = sm + OFF_A1F;
    float* a2c  = sm + OFF_A2C;
    float* a3r  = sm + OFF_A3R;
    float* d3   = sm + OFF_D3;
    float* o2   = sm + OFF_O2;
    float* o1own= sm + OFF_O1OWN;
    float* mb1  = sm + OFF_MB1;
    float* mb2  = sm + OFF_MB2;
    float* mb3  = sm + OFF_MB3;
    float* stg  = sm + OFF_STG;
    float* sred = sm + OFF_SRED;
    float* sres = sm + OFF_SRES;
    float* sq   = sm + OFF_SQ;
    float* sS   = sm + OFF_SS;
    float* snx  = sm + OFF_SNX;
    float* spart= sm + OFF_SPART;

    const int tid = threadIdx.x;
    const int w = tid >> 5, lane = tid & 31;

    uint32_t me;
    asm("mov.u32 %0, %%cluster_ctarank;" : "=r"(me));
    const uint32_t sbase = smem_u32(sm);
    const uint32_t ACC1A = sbase + OFF_ACC1 * 4;
    const uint32_t ACC2A = sbase + OFF_ACC2 * 4;
    const uint32_t O1FA  = sbase + OFF_O1F * 4;
    const uint32_t SPA   = sbase + OFF_SPART * 4;

    // ================= init =================
    for (int idx = tid; idx < C1 * Dd; idx += T) {
        int c = idx & 15, r = idx >> 4;
        m1[c * Dd + r] = W1g[r * Hh + me * C1 + c];
    }
    for (int idx = tid; idx < C1 * Hh; idx += T) {
        int c = idx & 15, i = idx >> 4;
        m2c[c * Hh + i] = W2g[i * Hh + me * C1 + c];
    }
    for (int idx = tid; idx < C1 * Hh; idx += T) {
        int r = idx >> 8, j = idx & 255;
        m2r[r * Hh + j] = W2g[(me * C1 + r) * Hh + j];
    }
    for (int idx = tid; idx < Oo * Hh; idx += T)
        m3[idx] = W3g[(idx & 255) * Oo + (idx >> 8)];
    if (tid < Hh) { mb1[tid] = b1g[tid]; mb2[tid] = b2g[tid]; o1f[tid] = 0.f; }
    if (tid < Oo) mb3[tid] = b3g[tid];
    if (tid < 6)  sq[tid] = 1.f;
    if (tid < 256) ((float4*)xb)[tid] = ((const float4*)X)[tid];
    else if (tid < 320) tgb[tid - 256] = Tg[tid - 256];
    __syncthreads();

    // ---- initial norm partials (7-way fused reduce) ----
    {
        float p1 = 0.f, p2 = 0.f, p3 = 0.f, pb1 = 0.f, pb2 = 0.f, pb3 = 0.f, px = 0.f;
        for (int idx = tid; idx < C1 * Dd; idx += T) { float v = m1[idx]; p1 += v * v; }
        for (int idx = tid; idx < C1 * Hh; idx += T) { float v = m2c[idx]; p2 += v * v; }
        for (int idx = tid; idx < Oo * Hh; idx += T) { float v = m3[idx]; p3 += v * v; }
        if (tid < Hh) { float a = mb1[tid], b = mb2[tid]; pb1 = a * a; pb2 = b * b; }
        if (tid < Oo) { float c = mb3[tid]; pb3 = c * c; }
        for (int i = tid; i < Dd; i += T) { float v = xb[i]; px += v * v; }
        float vals[7] = {p1, p2, p3, pb1, pb2, pb3, px};
        #pragma unroll
        for (int s = 0; s < 7; s++) vals[s] = warp_sum(vals[s]);
        if (lane == 0) {
            #pragma unroll
            for (int s = 0; s < 7; s++) sred[w * 9 + s] = vals[s];
        }
        __syncthreads();
        if (w < 7) {
            float v = (lane < 16) ? sred[lane * 9 + w] : 0.f;
            v = warp_sum(v);
            if (lane == 0) sres[w] = v;
        }
        __syncthreads();
        if (tid == 0) {
            sS[2] = sres[2]; sS[3] = sres[3]; sS[4] = sres[4]; sS[5] = sres[5];
            snx[0] = sres[6]; snx[1] = 0.f;
        }
    }
    // ---- prologue acc1(0) MV ----
    if (w < 16) {
        const float4* c4 = (const float4*)(m1 + w * Dd);
        const float4* x4 = (const float4*)xb;
        float acc = 0.f;
        #pragma unroll
        for (int k = 0; k < 8; k++) acc += dot4(c4[k * 32 + lane], x4[k * 32 + lane]);
        acc = warp_sum(acc);
        if (lane == 0) stg[w] = acc;
    }
    __syncthreads();
    CLUSTER_SYNC();   // all CTAs initialized before pushes
    if (tid < 256) st_peer(ACC1A + ((me * C1 + (tid >> 4)) << 2), tid & 15, stg[tid >> 4]);
    if (tid < 32) {   // push initial S1,S2 partials
        int k = tid >> 4, p = tid & 15;
        st_peer(SPA + ((me * 2 + k) << 2), p, sres[k]);
    }
    CLUSTER_ARRIVE();

    for (int step = 0; step < NSTEPS; ++step) {
        CLUSTER_WAIT();   // S_a: acc1r(step) + o1f(step-1) delivered
        const int par = step & 1;
        const float* xcur = xb + par * Dd;
        float* xnext = xb + (par ^ 1) * Dd;
        const float* acc1c = acc1 + par * Hh;
        const float* acc1p = acc1 + (par ^ 1) * Hh;

        // ---- item 1: layer-1 scalars (one warp per dot, parallel) ----
        const float q1o = sq[0], qb1o = sq[3];
        if (w == 0) {
            float acc = 0.f;
            #pragma unroll
            for (int k = 0; k < 8; k++) { int i = lane + 32 * k; acc += o1f[i] * acc1p[i]; }
            acc = warp_sum(acc);
            if (lane == 0) sres[0] = acc;
        } else if (w == 1) {
            float acc = 0.f;
            #pragma unroll
            for (int k = 0; k < 8; k++) { int i = lane + 32 * k; acc += mb1[i] * o1f[i]; }
            acc = warp_sum(acc);
            if (lane == 0) sres[1] = acc;
        } else if (w == 2) {
            float acc = 0.f;
            #pragma unroll
            for (int k = 0; k < 8; k++) { int i = lane + 32 * k; float v = o1f[i]; acc += v * v; }
            acc = warp_sum(acc);
            if (lane == 0) sres[2] = acc;
        }
        __syncthreads();
        if (tid == 0) {
            if (step == 0) {
                float s1 = 0.f, s2 = 0.f;
                #pragma unroll
                for (int p = 0; p < NC; p++) { s1 += spart[p * 2]; s2 += spart[p * 2 + 1]; }
                sS[0] = s1; sS[1] = s2;
            } else {
                float r1 = sres[0], r2 = sres[1], r3 = sres[2];
                float S1 = q1o * q1o * sS[0] - 2.f * LRc * q1o * r1
                         + LRc * LRc * snx[par ^ 1] * r3;
                sS[0] = S1; sq[0] = 1.f / fmaxf(sqrtf(S1), EPSc);
                float B1 = qb1o * qb1o * sS[3] - 2.f * LRc * qb1o * r2 + LRc * LRc * r3;
                sS[3] = B1; sq[3] = 1.f / fmaxf(sqrtf(B1), EPSc);
            }
        }
        __syncthreads();
        const float q1n = sq[0], qb1n = sq[3];

        // ---- item 2: b1 update + a1 (replicated) ----
        if (tid < Hh) {
            float v = qb1o * mb1[tid] - LRc * o1f[tid];
            mb1[tid] = v;
            a1f[tid] = sigmoidf(q1n * acc1c[tid] + qb1n * v);
        }
        __syncthreads();

        // ---- item 3: acc2 MV (raw), push, arrive ----
        if (w < 16) {
            const float4* a14 = (const float4*)a1f;
            const float4* c4 = (const float4*)(m2c + w * Hh);
            float acc = 0.f;
            #pragma unroll
            for (int k = 0; k < 2; k++) acc += dot4(c4[k * 32 + lane], a14[k * 32 + lane]);
            acc = warp_sum(acc);
            if (lane == 0) stg[w] = acc;
        }
        __syncthreads();
        if (tid < 256) st_peer(ACC2A + ((me * C1 + (tid >> 4)) << 2), tid & 15, stg[tid >> 4]);
        CLUSTER_ARRIVE();

        // ---- item 4: prefetch (hides S_b latency) ----
        if (step + 1 < NSTEPS) {
            if (tid < 256)
                ((float4*)xnext)[tid] = ((const float4*)(X + (step + 1) * Dd))[tid];
            else if (tid < 320)
                tgb[(par ^ 1) * Oo + (tid - 256)] = Tg[(step + 1) * Oo + (tid - 256)];
        }
        CLUSTER_WAIT();   // S_b

        // ---- item 5: a2 (replicated) ----
        const float q2o = sq[1], qb2o = sq[4], q3o = sq[2], qb3o = sq[5];
        if (tid < Hh) a2c[tid] = sigmoidf(q2o * acc2r[tid] + qb2o * mb2[tid]);
        __syncthreads();

        // ---- item 6: a3 raw MV (warps 0-15, 4 rows each) ----
        if (w < 16) {
            const float4* a24 = (const float4*)a2c;
            float acc[4] = {0.f, 0.f, 0.f, 0.f};
            #pragma unroll
            for (int s = 0; s < 4; s++) {
                const float4* r4 = (const float4*)(m3 + (w + 16 * s) * Hh);
                #pragma unroll
                for (int k = 0; k < 2; k++)
                    acc[s] += dot4(r4[k * 32 + lane], a24[k * 32 + lane]);
            }
            #pragma unroll
            for (int o = 16; o; o >>= 1) {
                #pragma unroll
                for (int s = 0; s < 4; s++)
                    acc[s] += __shfl_xor_sync(0xffffffffu, acc[s], o);
            }
            if (lane == 0) {
                #pragma unroll
                for (int s = 0; s < 4; s++) a3r[w + 16 * s] = acc[s];
            }
        }
        __syncthreads();

        // ---- item 7: sigmoid + softmax + d3 (warp 0) ----
        if (w == 0) {
            float a30 = sigmoidf(q3o * a3r[lane] + qb3o * mb3[lane]);
            float a31 = sigmoidf(q3o * a3r[lane + 32] + qb3o * mb3[lane + 32]);
            const float* tgc = tgb + par * Oo;
            float t0 = tgc[lane], t1 = tgc[lane + 32];
            float m = fmaxf(-a30, -a31);
            #pragma unroll
            for (int o = 16; o; o >>= 1) m = fmaxf(m, __shfl_xor_sync(0xffffffffu, m, o));
            float e0 = expf(-a30 - m), e1 = expf(-a31 - m);
            float s = warp_sum(e0 + e1);
            float inv = 1.f / s;
            d3[lane]      = (t0 - e0 * inv) * a30 * (1.f - a30);
            d3[lane + 32] = (t1 - e1 * inv) * a31 * (1.f - a31);
        }
        __syncthreads();

        // ---- item 8: o2 (pre-update m3) ----
        if (tid < Hh) {
            const float* col = m3 + tid;
            float r0 = 0.f, r1 = 0.f, r2 = 0.f, r3 = 0.f;
            #pragma unroll
            for (int j = 0; j < Oo; j += 4) {
                r0 += col[(j + 0) * Hh] * d3[j + 0];
                r1 += col[(j + 1) * Hh] * d3[j + 1];
                r2 += col[(j + 2) * Hh] * d3[j + 2];
                r3 += col[(j + 3) * Hh] * d3[j + 3];
            }
            float raw = (r0 + r1) + (r2 + r3);
            float a = a2c[tid];
            o2[tid] = q3o * raw * a * (1.f - a);
        }
        __syncthreads();

        // ---- items 9+10 fused: o1 (warps 0-7) || norm dots (warps 8-14) ----
        if (w < 8) {
            const float4* o24 = (const float4*)o2;
            const float4* rA = (const float4*)(m2r + (2 * w) * Hh);
            const float4* rB = (const float4*)(m2r + (2 * w + 1) * Hh);
            float aA = 0.f, aB = 0.f;
            #pragma unroll
            for (int k = 0; k < 2; k++) {
                float4 ov = o24[k * 32 + lane];
                aA += dot4(rA[k * 32 + lane], ov);
                aB += dot4(rB[k * 32 + lane], ov);
            }
            aA = warp_sum(aA); aB = warp_sum(aB);
            if (lane == 0) {
                float a1A = a1f[me * C1 + 2 * w];
                float a1B = a1f[me * C1 + 2 * w + 1];
                o1own[2 * w]     = q2o * aA * a1A * (1.f - a1A);
                o1own[2 * w + 1] = q2o * aB * a1B * (1.f - a1B);
            }
        } else if (w == 8) {
            float acc = 0.f;
            #pragma unroll
            for (int k = 0; k < 8; k++) { int i = lane + 32 * k; acc += o2[i] * acc2r[i]; }
            acc = warp_sum(acc);
            if (lane == 0) sres[0] = acc;
        } else if (w == 9) {
            float acc = 0.f;
            #pragma unroll
            for (int k = 0; k < 8; k++) { int i = lane + 32 * k; float v = o2[i]; acc += v * v; }
            acc = warp_sum(acc);
            if (lane == 0) sres[1] = acc;
        } else if (w == 10) {
            float acc = 0.f;
            #pragma unroll
            for (int k = 0; k < 8; k++) { int i = lane + 32 * k; acc += mb2[i] * o2[i]; }
            acc = warp_sum(acc);
            if (lane == 0) sres[2] = acc;
        } else if (w == 11) {
            float acc = 0.f;
            #pragma unroll
            for (int k = 0; k < 8; k++) { int i = lane + 32 * k; float v = a1f[i]; acc += v * v; }
            acc = warp_sum(acc);
            if (lane == 0) sres[3] = acc;
        } else if (w == 12) {
            float a4 = 0.f, a5 = 0.f;
            #pragma unroll
            for (int k = 0; k < 2; k++) {
                int i = lane + 32 * k;
                float dv = d3[i];
                a4 += dv * a3r[i]; a5 += dv * dv;
            }
            a4 = warp_sum(a4); a5 = warp_sum(a5);
            if (lane == 0) { sres[4] = a4; sres[5] = a5; }
        } else if (w == 13) {
            float a6 = 0.f, a7 = 0.f;
            #pragma unroll
            for (int k = 0; k < 2; k++) { int i = lane + 32 * k; a6 += mb3[i] * d3[i]; }
            #pragma unroll
            for (int k = 0; k < 8; k++) { int i = lane + 32 * k; float v = a2c[i]; a7 += v * v; }
            a6 = warp_sum(a6); a7 = warp_sum(a7);
            if (lane == 0) { sres[6] = a6; sres[7] = a7; }
        } else if (w == 14) {
            const float4* xn4 = (const float4*)xnext;
            float acc = 0.f;
            #pragma unroll
            for (int k = 0; k < 8; k++) { float4 v = xn4[lane + 32 * k]; acc += dot4(v, v); }
            acc = warp_sum(acc);
            if (lane == 0) sres[8] = acc;
        }
        __syncthreads();

        // ---- scalar recurrences + b2/b3 updates ----
        if (tid == 0) {
            float S2 = q2o * q2o * sS[1] - 2.f * LRc * q2o * sres[0]
                     + LRc * LRc * sres[3] * sres[1];
            sS[1] = S2; sq[1] = 1.f / fmaxf(sqrtf(S2), EPSc);
            float B2 = qb2o * qb2o * sS[4] - 2.f * LRc * qb2o * sres[2]
                     + LRc * LRc * sres[1];
            sS[4] = B2; sq[4] = 1.f / fmaxf(sqrtf(B2), EPSc);
            float S3 = q3o * q3o * sS[2] - 2.f * LRc * q3o * sres[4]
                     + LRc * LRc * sres[7] * sres[5];
            sS[2] = S3; sq[2] = 1.f / fmaxf(sqrtf(S3), EPSc);
            float B3 = qb3o * qb3o * sS[5] - 2.f * LRc * qb3o * sres[6]
                     + LRc * LRc * sres[5];
            sS[5] = B3; sq[5] = 1.f / fmaxf(sqrtf(B3), EPSc);
            snx[par ^ 1] = sres[8];
        }
        if (tid < Hh) mb2[tid] = qb2o * mb2[tid] - LRc * o2[tid];
        if (tid < Oo) mb3[tid] = qb3o * mb3[tid] - LRc * d3[tid];
        __syncthreads();

        // ---- tail (a+b fused): W1 col update + next-step MV, warp-per-col ----
        {
            float sv = LRc * o1own[w];
            float4* c4 = (float4*)(m1 + w * Dd);
            const float4* xc4 = (const float4*)xcur;
            const float4* xn4 = (const float4*)xnext;
            float acc = 0.f;
            #pragma unroll
            for (int k = 0; k < 8; k++) {
                int ii = k * 32 + lane;
                float4 wv = c4[ii], xv = xc4[ii];
                wv.x = q1n * wv.x - sv * xv.x;
                wv.y = q1n * wv.y - sv * xv.y;
                wv.z = q1n * wv.z - sv * xv.z;
                wv.w = q1n * wv.w - sv * xv.w;
                c4[ii] = wv;
                acc += dot4(wv, xn4[ii]);
            }
            acc = warp_sum(acc);
            if (lane == 0) stg[w] = acc;
        }
        __syncthreads();
        // ---- tail (c): pushes + arrive ----
        if (tid < 256) {
            int j = tid >> 4, p = tid & 15;
            st_peer(ACC1A + ((((par ^ 1) * Hh) + me * C1 + j) << 2), p, stg[j]);
            st_peer(O1FA + ((me * C1 + j) << 2), p, o1own[j]);
        }
        CLUSTER_ARRIVE();
        // ---- tail (d): W3 update ----
        {
            float4* m34 = (float4*)m3;
            const float4* a24 = (const float4*)a2c;
            #pragma unroll
            for (int k = 0; k < 8; k++) {
                int e4 = tid + 512 * k;
                int j = e4 >> 6, i4 = e4 & 63;
                float sv = LRc * d3[j];
                float4 wv = m34[e4], av = a24[i4];
                wv.x = q3o * wv.x - sv * av.x;
                wv.y = q3o * wv.y - sv * av.y;
                wv.z = q3o * wv.z - sv * av.z;
                wv.w = q3o * wv.w - sv * av.w;
                m34[e4] = wv;
            }
        }
        // ---- tail (e): W2 col update ----
        {
            float4* c4 = (float4*)m2c;
            const float4* a14 = (const float4*)a1f;
            #pragma unroll
            for (int k = 0; k < 2; k++) {
                int e4 = tid + 512 * k;
                int c = e4 >> 6, i4 = e4 & 63;
                float sv = LRc * o2[me * C1 + c];
                float4 wv = c4[e4], av = a14[i4];
                wv.x = q2o * wv.x - sv * av.x;
                wv.y = q2o * wv.y - sv * av.y;
                wv.z = q2o * wv.z - sv * av.z;
                wv.w = q2o * wv.w - sv * av.w;
                c4[e4] = wv;
            }
        }
        // ---- tail (f): W2 row update ----
        {
            float4* r4 = (float4*)m2r;
            const float4* o24 = (const float4*)o2;
            #pragma unroll
            for (int k = 0; k < 2; k++) {
                int e4 = tid + 512 * k;
                int r = e4 >> 6, j4 = e4 & 63;
                float sv = LRc * a1f[me * C1 + r];
                float4 wv = r4[e4], ov = o24[j4];
                wv.x = q2o * wv.x - sv * ov.x;
                wv.y = q2o * wv.y - sv * ov.y;
                wv.z = q2o * wv.z - sv * ov.z;
                wv.w = q2o * wv.w - sv * ov.w;
                r4[e4] = wv;
            }
        }
        __syncthreads();
    }

    CLUSTER_WAIT();   // pair the final arrive; delivers o1f(1023) + acc1r(1023) intact
    // final q1 via closed form (o1f(1023), acc1r in parity-1 buffer, ||x_1023||^2 in snx[1])
    {
        const float q1o = sq[0];
        const float* a1p = acc1 + 1 * Hh;
        float v0 = 0.f, v2 = 0.f;
        if (tid < Hh) { float ov = o1f[tid]; v0 = ov * a1p[tid]; v2 = ov * ov; }
        v0 = warp_sum(v0); v2 = warp_sum(v2);
        if (lane == 0) { sred[w * 9] = v0; sred[w * 9 + 1] = v2; }
        __syncthreads();
        if (w < 2) {
            float v = (lane < 16) ? sred[lane * 9 + w] : 0.f;
            v = warp_sum(v);
            if (lane == 0) sres[w] = v;
        }
        __syncthreads();
        if (tid == 0) {
            float S1 = q1o * q1o * sS[0] - 2.f * LRc * q1o * sres[0]
                     + LRc * LRc * snx[1] * sres[1];
            sq[0] = 1.f / fmaxf(sqrtf(S1), EPSc);
        }
        __syncthreads();
    }
    const float q1f = sq[0], q2f = sq[1], q3f = sq[2];

    // ---- write out: W1 | W2 | W3 (row-major), guarded, sanitized ----
    for (int idx = tid; idx < C1 * Dd; idx += T) {
        int c = idx & 15, r = idx >> 4;
        int o = r * Hh + me * C1 + c;
        if (o < out_size) out[o] = sanitize(q1f * m1[c * Dd + r]);
    }
    for (int idx = tid; idx < C1 * Hh; idx += T) {
        int c = idx & 15, i = idx >> 4;
        int o = Dd * Hh + i * Hh + me * C1 + c;
        if (o < out_size) out[o] = sanitize(q2f * m2c[c * Hh + i]);
    }
    for (int idx = tid; idx < 4 * Hh; idx += T) {
        int j = (int)me * 4 + (idx & 3), i = idx >> 2;
        int o = Dd * Hh + Hh * Hh + i * Oo + j;
        if (o < out_size) out[o] = sanitize(q3f * m3[j * Hh + i]);
    }
    for (int o = TOTAL_OUT + (int)me * T + tid; o < out_size; o += NC * T) out[o] = 0.f;
}

extern "C" void kernel_launch(void* const* d_in, const int* in_sizes, int n_in,
                              void* d_out, int out_size) {
    const float* X = 0; const float* Tg = 0;
    const float* W1 = 0; const float* b1 = 0;
    const float* W2 = 0; const float* b2 = 0;
    const float* W3 = 0; const float* b3 = 0;
    for (int i = 0; i < n_in; i++) {
        const float* p = (const float*)d_in[i];
        switch (in_sizes[i]) {
            case 1024 * 1024: X = p; break;
            case 1024 * 256:  W1 = p; break;
            case 256 * 256:   if (!Tg) Tg = p; else W2 = p; break;
            case 256 * 64:    W3 = p; break;
            case 256:         if (!b1) b1 = p; else b2 = p; break;
            case 64:          b3 = p; break;
            default: break;
        }
    }
    cudaFuncSetAttribute(train_kernel, cudaFuncAttributeMaxDynamicSharedMemorySize, SMEM_BYTES);
    cudaFuncSetAttribute(train_kernel, cudaFuncAttributeNonPortableClusterSizeAllowed, 1);

    cudaLaunchConfig_t cfg = {};
    cfg.gridDim = dim3(NC, 1, 1);
    cfg.blockDim = dim3(T, 1, 1);
    cfg.dynamicSmemBytes = SMEM_BYTES;
    cudaLaunchAttribute attrs[1];
    attrs[0].id = cudaLaunchAttributeClusterDimension;
    attrs[0].val.clusterDim.x = NC;
    attrs[0].val.clusterDim.y = 1;
    attrs[0].val.clusterDim.z = 1;
    cfg.attrs = attrs;
    cfg.numAttrs = 1;
    cudaLaunchKernelEx(&cfg, train_kernel, X, Tg, W1, b1, W2, b2, W3, b3,
                       (float*)d_out, out_size);
}

// round 17
// speedup vs baseline: 1.5523x; 1.0464x over previous
#include <cuda_runtime.h>
#include <math.h>
#include <cstdint>

// 16-CTA cluster, persistent, bulk-synchronous, TWO cluster syncs per step.
// W1/W2 col-sliced, W2 also row-sliced, W3 replicated. RAW preactivations
// exchanged (replicated), sigmoids computed replicated. Norms via exact
// closed-form recurrences. R17: __expf sigmoid/softmax (MUFU.EX2), softmax
// max-subtraction removed (shift-invariant, args bounded), all-thread local
// scalar recomputation (removes tid0 serialization + 2 barriers/step).

#define NC 16
#define T  512
#define Dd 1024
#define Hh 256
#define Oo 64
#define NSTEPS 1024
#define LRc 0.01f
#define EPSc 1e-8f
#define C1 16
#define TOTAL_OUT (Dd * Hh + Hh * Hh + Hh * Oo)   // 344064

// ---- SMEM layout (float offsets) ----
#define OFF_M1    0        // [C1][Dd]                         16384
#define OFF_M2C   16384    // [C1][Hh]                          4096
#define OFF_M2R   20480    // [C1][Hh]                          4096
#define OFF_M3    24576    // [Oo][Hh]                         16384
#define OFF_X     40960    // [2][Dd]                           2048
#define OFF_TG    43008    // [2][Oo]                            128
#define OFF_ACC1  43136    // [2][Hh] pushed raw l1 preacts      512
#define OFF_ACC2  43648    // [Hh] pushed raw l2 preacts         256
#define OFF_O1F   43904    // [Hh] pushed o1 full                256
#define OFF_A1F   44160    // [Hh]                               256
#define OFF_A2C   44416    // [Hh]                               256
#define OFF_A3R   44672    // [Oo] raw l3 preacts                 64
#define OFF_D3    44736    // [Oo]                                64
#define OFF_O2    44800    // [Hh]                               256
#define OFF_O1OWN 45056    // [C1]                                16
#define OFF_MB1   45072    // [Hh] replicated                    256
#define OFF_MB2   45328    // [Hh]                               256
#define OFF_MB3   45584    // [Oo]                                64
#define OFF_STG   45648    // [C1]                                16
#define OFF_SRED  45664    // [16][9]                            144
#define OFF_SRES  45808    // [9]                                  9
#define OFF_SQ    45817    // q1,q2,q3,qb1,qb2,qb3                 6
#define OFF_SS    45823    // S1,S2,S3,BN1,BN2,BN3                 6
#define OFF_SNX   45829    // ||x||^2 parity pair                  2
#define OFF_SPART 45832    // [NC][2] init-only pushed S1,S2 par  32
#define SMEM_FLOATS 45864
#define SMEM_BYTES (SMEM_FLOATS * 4)

__device__ __forceinline__ uint32_t smem_u32(const void* p) {
    uint32_t a;
    asm("{ .reg .u64 t; cvta.to.shared.u64 t, %1; cvt.u32.u64 %0, t; }"
        : "=r"(a) : "l"(p));
    return a;
}
__device__ __forceinline__ void st_peer(uint32_t laddr, uint32_t rank, float v) {
    uint32_t r;
    asm volatile("mapa.shared::cluster.u32 %0, %1, %2;" : "=r"(r) : "r"(laddr), "r"(rank));
    asm volatile("st.shared::cluster.f32 [%0], %1;" :: "r"(r), "f"(v) : "memory");
}
#define CLUSTER_SYNC() do { \
    asm volatile("barrier.cluster.arrive.aligned;" ::: "memory"); \
    asm volatile("barrier.cluster.wait.aligned;" ::: "memory");   \
} while (0)
#define CLUSTER_ARRIVE() asm volatile("barrier.cluster.arrive.aligned;" ::: "memory")
#define CLUSTER_WAIT()   asm volatile("barrier.cluster.wait.aligned;" ::: "memory")

__device__ __forceinline__ float warp_sum(float v) {
    #pragma unroll
    for (int o = 16; o; o >>= 1) v += __shfl_xor_sync(0xffffffffu, v, o);
    return v;
}
__device__ __forceinline__ float sigmoidf(float p) { return 1.f / (1.f + __expf(-p)); }
__device__ __forceinline__ float sanitize(float v) { return isfinite(v) ? v : 0.f; }
__device__ __forceinline__ float dot4(float4 a, float4 b) {
    return a.x * b.x + a.y * b.y + a.z * b.z + a.w * b.w;
}

__global__ void __launch_bounds__(T, 1)
train_kernel(const float* __restrict__ X, const float* __restrict__ Tg,
             const float* __restrict__ W1g, const float* __restrict__ b1g,
             const float* __restrict__ W2g, const float* __restrict__ b2g,
             const float* __restrict__ W3g, const float* __restrict__ b3g,
             float* __restrict__ out, int out_size)
{
    extern __shared__ float sm[];
    float* m1   = sm + OFF_M1;
    float* m2c  = sm + OFF_M2C;
    float* m2r  = sm + OFF_M2R;
    float* m3   = sm + OFF_M3;
    float* xb   = sm + OFF_X;
    float* tgb  = sm + OFF_TG;
    float* acc1 = sm + OFF_ACC1;
    float* acc2r= sm + OFF_ACC2;
    float* o1f  = sm + OFF_O1F;
    float* a1f  = sm + OFF_A1F;
    float* a2c  = sm + OFF_A2C;
    float* a3r  = sm + OFF_A3R;
    float* d3   = sm + OFF_D3;
    float* o2   = sm + OFF_O2;
    float* o1own= sm + OFF_O1OWN;
    float* mb1  = sm + OFF_MB1;
    float* mb2  = sm + OFF_MB2;
    float* mb3  = sm + OFF_MB3;
    float* stg  = sm + OFF_STG;
    float* sred = sm + OFF_SRED;
    float* sres = sm + OFF_SRES;
    float* sq   = sm + OFF_SQ;
    float* sS   = sm + OFF_SS;
    float* snx  = sm + OFF_SNX;
    float* spart= sm + OFF_SPART;

    const int tid = threadIdx.x;
    const int w = tid >> 5, lane = tid & 31;

    uint32_t me;
    asm("mov.u32 %0, %%cluster_ctarank;" : "=r"(me));
    const uint32_t sbase = smem_u32(sm);
    const uint32_t ACC1A = sbase + OFF_ACC1 * 4;
    const uint32_t ACC2A = sbase + OFF_ACC2 * 4;
    const uint32_t O1FA  = sbase + OFF_O1F * 4;
    const uint32_t SPA   = sbase + OFF_SPART * 4;

    // ================= init =================
    for (int idx = tid; idx < C1 * Dd; idx += T) {
        int c = idx & 15, r = idx >> 4;
        m1[c * Dd + r] = W1g[r * Hh + me * C1 + c];
    }
    for (int idx = tid; idx < C1 * Hh; idx += T) {
        int c = idx & 15, i = idx >> 4;
        m2c[c * Hh + i] = W2g[i * Hh + me * C1 + c];
    }
    for (int idx = tid; idx < C1 * Hh; idx += T) {
        int r = idx >> 8, j = idx & 255;
        m2r[r * Hh + j] = W2g[(me * C1 + r) * Hh + j];
    }
    for (int idx = tid; idx < Oo * Hh; idx += T)
        m3[idx] = W3g[(idx & 255) * Oo + (idx >> 8)];
    if (tid < Hh) { mb1[tid] = b1g[tid]; mb2[tid] = b2g[tid]; o1f[tid] = 0.f; }
    if (tid < Oo) mb3[tid] = b3g[tid];
    if (tid < 6)  sq[tid] = 1.f;
    if (tid < 256) ((float4*)xb)[tid] = ((const float4*)X)[tid];
    else if (tid < 320) tgb[tid - 256] = Tg[tid - 256];
    __syncthreads();

    // ---- initial norm partials (7-way fused reduce) ----
    {
        float p1 = 0.f, p2 = 0.f, p3 = 0.f, pb1 = 0.f, pb2 = 0.f, pb3 = 0.f, px = 0.f;
        for (int idx = tid; idx < C1 * Dd; idx += T) { float v = m1[idx]; p1 += v * v; }
        for (int idx = tid; idx < C1 * Hh; idx += T) { float v = m2c[idx]; p2 += v * v; }
        for (int idx = tid; idx < Oo * Hh; idx += T) { float v = m3[idx]; p3 += v * v; }
        if (tid < Hh) { float a = mb1[tid], b = mb2[tid]; pb1 = a * a; pb2 = b * b; }
        if (tid < Oo) { float c = mb3[tid]; pb3 = c * c; }
        for (int i = tid; i < Dd; i += T) { float v = xb[i]; px += v * v; }
        float vals[7] = {p1, p2, p3, pb1, pb2, pb3, px};
        #pragma unroll
        for (int s = 0; s < 7; s++) vals[s] = warp_sum(vals[s]);
        if (lane == 0) {
            #pragma unroll
            for (int s = 0; s < 7; s++) sred[w * 9 + s] = vals[s];
        }
        __syncthreads();
        if (w < 7) {
            float v = (lane < 16) ? sred[lane * 9 + w] : 0.f;
            v = warp_sum(v);
            if (lane == 0) sres[w] = v;
        }
        __syncthreads();
        if (tid == 0) {
            sS[2] = sres[2]; sS[3] = sres[3]; sS[4] = sres[4]; sS[5] = sres[5];
            snx[0] = sres[6]; snx[1] = 0.f;
        }
    }
    // ---- prologue acc1(0) MV ----
    if (w < 16) {
        const float4* c4 = (const float4*)(m1 + w * Dd);
        const float4* x4 = (const float4*)xb;
        float acc = 0.f;
        #pragma unroll
        for (int k = 0; k < 8; k++) acc += dot4(c4[k * 32 + lane], x4[k * 32 + lane]);
        acc = warp_sum(acc);
        if (lane == 0) stg[w] = acc;
    }
    __syncthreads();
    CLUSTER_SYNC();   // all CTAs initialized before pushes
    if (tid < 256) st_peer(ACC1A + ((me * C1 + (tid >> 4)) << 2), tid & 15, stg[tid >> 4]);
    if (tid < 32) {   // push initial S1,S2 partials
        int k = tid >> 4, p = tid & 15;
        st_peer(SPA + ((me * 2 + k) << 2), p, sres[k]);
    }
    CLUSTER_ARRIVE();

    for (int step = 0; step < NSTEPS; ++step) {
        CLUSTER_WAIT();   // S_a: acc1r(step) + o1f(step-1) delivered
        const int par = step & 1;
        const float* xcur = xb + par * Dd;
        float* xnext = xb + (par ^ 1) * Dd;
        const float* acc1c = acc1 + par * Hh;
        const float* acc1p = acc1 + (par ^ 1) * Hh;

        // ---- item 1: layer-1 dots (warps 0-2 parallel) ----
        const float q1o = sq[0], qb1o = sq[3];
        if (w == 0) {
            float acc = 0.f;
            #pragma unroll
            for (int k = 0; k < 8; k++) { int i = lane + 32 * k; acc += o1f[i] * acc1p[i]; }
            acc = warp_sum(acc);
            if (lane == 0) sres[0] = acc;
        } else if (w == 1) {
            float acc = 0.f;
            #pragma unroll
            for (int k = 0; k < 8; k++) { int i = lane + 32 * k; acc += mb1[i] * o1f[i]; }
            acc = warp_sum(acc);
            if (lane == 0) sres[1] = acc;
        } else if (w == 2) {
            float acc = 0.f;
            #pragma unroll
            for (int k = 0; k < 8; k++) { int i = lane + 32 * k; float v = o1f[i]; acc += v * v; }
            acc = warp_sum(acc);
            if (lane == 0) sres[2] = acc;
        }
        __syncthreads();

        // ---- layer-1 scalars: ALL threads compute locally (no 2nd bar) ----
        float q1n, qb1n;
        if (step == 0) {
            q1n = 1.f; qb1n = 1.f;
            if (tid == 0) {
                float s1 = 0.f, s2 = 0.f;
                #pragma unroll
                for (int p = 0; p < NC; p++) { s1 += spart[p * 2]; s2 += spart[p * 2 + 1]; }
                sS[0] = s1; sS[1] = s2;
            }
        } else {
            float r1 = sres[0], r2 = sres[1], r3 = sres[2];
            float S1 = q1o * q1o * sS[0] - 2.f * LRc * q1o * r1
                     + LRc * LRc * snx[par ^ 1] * r3;
            q1n = 1.f / fmaxf(sqrtf(S1), EPSc);
            float B1 = qb1o * qb1o * sS[3] - 2.f * LRc * qb1o * r2 + LRc * LRc * r3;
            qb1n = 1.f / fmaxf(sqrtf(B1), EPSc);
            if (tid == 0) { sS[0] = S1; sS[3] = B1; sq[0] = q1n; sq[3] = qb1n; }
        }

        // ---- item 2: b1 update + a1 (replicated) ----
        if (tid < Hh) {
            float v = qb1o * mb1[tid] - LRc * o1f[tid];
            mb1[tid] = v;
            a1f[tid] = sigmoidf(q1n * acc1c[tid] + qb1n * v);
        }
        __syncthreads();

        // ---- item 3: acc2 MV (raw), push, arrive ----
        if (w < 16) {
            const float4* a14 = (const float4*)a1f;
            const float4* c4 = (const float4*)(m2c + w * Hh);
            float acc = 0.f;
            #pragma unroll
            for (int k = 0; k < 2; k++) acc += dot4(c4[k * 32 + lane], a14[k * 32 + lane]);
            acc = warp_sum(acc);
            if (lane == 0) stg[w] = acc;
        }
        __syncthreads();
        if (tid < 256) st_peer(ACC2A + ((me * C1 + (tid >> 4)) << 2), tid & 15, stg[tid >> 4]);
        CLUSTER_ARRIVE();

        // ---- item 4: prefetch (hides S_b latency) ----
        if (step + 1 < NSTEPS) {
            if (tid < 256)
                ((float4*)xnext)[tid] = ((const float4*)(X + (step + 1) * Dd))[tid];
            else if (tid < 320)
                tgb[(par ^ 1) * Oo + (tid - 256)] = Tg[(step + 1) * Oo + (tid - 256)];
        }
        CLUSTER_WAIT();   // S_b

        // ---- item 5: a2 (replicated) ----
        const float q2o = sq[1], qb2o = sq[4], q3o = sq[2], qb3o = sq[5];
        if (tid < Hh) a2c[tid] = sigmoidf(q2o * acc2r[tid] + qb2o * mb2[tid]);
        __syncthreads();

        // ---- item 6: a3 raw MV (warps 0-15, 4 rows each) ----
        if (w < 16) {
            const float4* a24 = (const float4*)a2c;
            float acc[4] = {0.f, 0.f, 0.f, 0.f};
            #pragma unroll
            for (int s = 0; s < 4; s++) {
                const float4* r4 = (const float4*)(m3 + (w + 16 * s) * Hh);
                #pragma unroll
                for (int k = 0; k < 2; k++)
                    acc[s] += dot4(r4[k * 32 + lane], a24[k * 32 + lane]);
            }
            #pragma unroll
            for (int o = 16; o; o >>= 1) {
                #pragma unroll
                for (int s = 0; s < 4; s++)
                    acc[s] += __shfl_xor_sync(0xffffffffu, acc[s], o);
            }
            if (lane == 0) {
                #pragma unroll
                for (int s = 0; s < 4; s++) a3r[w + 16 * s] = acc[s];
            }
        }
        __syncthreads();

        // ---- item 7: sigmoid + softmax + d3 (warp 0, no max-shift) ----
        if (w == 0) {
            float a30 = sigmoidf(q3o * a3r[lane] + qb3o * mb3[lane]);
            float a31 = sigmoidf(q3o * a3r[lane + 32] + qb3o * mb3[lane + 32]);
            const float* tgc = tgb + par * Oo;
            float t0 = tgc[lane], t1 = tgc[lane + 32];
            float e0 = __expf(-a30), e1 = __expf(-a31);   // args in (-1,0): safe
            float s = warp_sum(e0 + e1);
            float inv = 1.f / s;
            d3[lane]      = (t0 - e0 * inv) * a30 * (1.f - a30);
            d3[lane + 32] = (t1 - e1 * inv) * a31 * (1.f - a31);
        }
        __syncthreads();

        // ---- item 8: o2 (pre-update m3) ----
        if (tid < Hh) {
            const float* col = m3 + tid;
            float r0 = 0.f, r1 = 0.f, r2 = 0.f, r3 = 0.f;
            #pragma unroll
            for (int j = 0; j < Oo; j += 4) {
                r0 += col[(j + 0) * Hh] * d3[j + 0];
                r1 += col[(j + 1) * Hh] * d3[j + 1];
                r2 += col[(j + 2) * Hh] * d3[j + 2];
                r3 += col[(j + 3) * Hh] * d3[j + 3];
            }
            float raw = (r0 + r1) + (r2 + r3);
            float a = a2c[tid];
            o2[tid] = q3o * raw * a * (1.f - a);
        }
        __syncthreads();

        // ---- items 9+10 fused: o1 (warps 0-7) || norm dots (warps 8-14) ----
        if (w < 8) {
            const float4* o24 = (const float4*)o2;
            const float4* rA = (const float4*)(m2r + (2 * w) * Hh);
            const float4* rB = (const float4*)(m2r + (2 * w + 1) * Hh);
            float aA = 0.f, aB = 0.f;
            #pragma unroll
            for (int k = 0; k < 2; k++) {
                float4 ov = o24[k * 32 + lane];
                aA += dot4(rA[k * 32 + lane], ov);
                aB += dot4(rB[k * 32 + lane], ov);
            }
            aA = warp_sum(aA); aB = warp_sum(aB);
            if (lane == 0) {
                float a1A = a1f[me * C1 + 2 * w];
                float a1B = a1f[me * C1 + 2 * w + 1];
                o1own[2 * w]     = q2o * aA * a1A * (1.f - a1A);
                o1own[2 * w + 1] = q2o * aB * a1B * (1.f - a1B);
            }
        } else if (w == 8) {
            float acc = 0.f;
            #pragma unroll
            for (int k = 0; k < 8; k++) { int i = lane + 32 * k; acc += o2[i] * acc2r[i]; }
            acc = warp_sum(acc);
            if (lane == 0) sres[0] = acc;
        } else if (w == 9) {
            float acc = 0.f;
            #pragma unroll
            for (int k = 0; k < 8; k++) { int i = lane + 32 * k; float v = o2[i]; acc += v * v; }
            acc = warp_sum(acc);
            if (lane == 0) sres[1] = acc;
        } else if (w == 10) {
            float acc = 0.f;
            #pragma unroll
            for (int k = 0; k < 8; k++) { int i = lane + 32 * k; acc += mb2[i] * o2[i]; }
            acc = warp_sum(acc);
            if (lane == 0) sres[2] = acc;
        } else if (w == 11) {
            float acc = 0.f;
            #pragma unroll
            for (int k = 0; k < 8; k++) { int i = lane + 32 * k; float v = a1f[i]; acc += v * v; }
            acc = warp_sum(acc);
            if (lane == 0) sres[3] = acc;
        } else if (w == 12) {
            float a4 = 0.f, a5 = 0.f;
            #pragma unroll
            for (int k = 0; k < 2; k++) {
                int i = lane + 32 * k;
                float dv = d3[i];
                a4 += dv * a3r[i]; a5 += dv * dv;
            }
            a4 = warp_sum(a4); a5 = warp_sum(a5);
            if (lane == 0) { sres[4] = a4; sres[5] = a5; }
        } else if (w == 13) {
            float a6 = 0.f, a7 = 0.f;
            #pragma unroll
            for (int k = 0; k < 2; k++) { int i = lane + 32 * k; a6 += mb3[i] * d3[i]; }
            #pragma unroll
            for (int k = 0; k < 8; k++) { int i = lane + 32 * k; float v = a2c[i]; a7 += v * v; }
            a6 = warp_sum(a6); a7 = warp_sum(a7);
            if (lane == 0) { sres[6] = a6; sres[7] = a7; }
        } else if (w == 14) {
            const float4* xn4 = (const float4*)xnext;
            float acc = 0.f;
            #pragma unroll
            for (int k = 0; k < 8; k++) { float4 v = xn4[lane + 32 * k]; acc += dot4(v, v); }
            acc = warp_sum(acc);
            if (lane == 0) sres[8] = acc;
        }
        __syncthreads();

        // ---- scalar recurrences (tid0 persists; no trailing bar) + b2/b3 ----
        if (tid == 0) {
            float S2 = q2o * q2o * sS[1] - 2.f * LRc * q2o * sres[0]
                     + LRc * LRc * sres[3] * sres[1];
            sS[1] = S2; sq[1] = 1.f / fmaxf(sqrtf(S2), EPSc);
            float B2 = qb2o * qb2o * sS[4] - 2.f * LRc * qb2o * sres[2]
                     + LRc * LRc * sres[1];
            sS[4] = B2; sq[4] = 1.f / fmaxf(sqrtf(B2), EPSc);
            float S3 = q3o * q3o * sS[2] - 2.f * LRc * q3o * sres[4]
                     + LRc * LRc * sres[7] * sres[5];
            sS[2] = S3; sq[2] = 1.f / fmaxf(sqrtf(S3), EPSc);
            float B3 = qb3o * qb3o * sS[5] - 2.f * LRc * qb3o * sres[6]
                     + LRc * LRc * sres[5];
            sS[5] = B3; sq[5] = 1.f / fmaxf(sqrtf(B3), EPSc);
            snx[par ^ 1] = sres[8];
        }
        if (tid < Hh) mb2[tid] = qb2o * mb2[tid] - LRc * o2[tid];
        if (tid < Oo) mb3[tid] = qb3o * mb3[tid] - LRc * d3[tid];

        // ---- tail (a+b fused): W1 col update + next-step MV, warp-per-col ----
        {
            float sv = LRc * o1own[w];
            float4* c4 = (float4*)(m1 + w * Dd);
            const float4* xc4 = (const float4*)xcur;
            const float4* xn4 = (const float4*)xnext;
            float acc = 0.f;
            #pragma unroll
            for (int k = 0; k < 8; k++) {
                int ii = k * 32 + lane;
                float4 wv = c4[ii], xv = xc4[ii];
                wv.x = q1n * wv.x - sv * xv.x;
                wv.y = q1n * wv.y - sv * xv.y;
                wv.z = q1n * wv.z - sv * xv.z;
                wv.w = q1n * wv.w - sv * xv.w;
                c4[ii] = wv;
                acc += dot4(wv, xn4[ii]);
            }
            acc = warp_sum(acc);
            if (lane == 0) stg[w] = acc;
        }
        __syncthreads();
        // ---- tail (c): pushes + arrive ----
        if (tid < 256) {
            int j = tid >> 4, p = tid & 15;
            st_peer(ACC1A + ((((par ^ 1) * Hh) + me * C1 + j) << 2), p, stg[j]);
            st_peer(O1FA + ((me * C1 + j) << 2), p, o1own[j]);
        }
        CLUSTER_ARRIVE();
        // ---- tail (d): W3 update ----
        {
            float4* m34 = (float4*)m3;
            const float4* a24 = (const float4*)a2c;
            #pragma unroll
            for (int k = 0; k < 8; k++) {
                int e4 = tid + 512 * k;
                int j = e4 >> 6, i4 = e4 & 63;
                float sv = LRc * d3[j];
                float4 wv = m34[e4], av = a24[i4];
                wv.x = q3o * wv.x - sv * av.x;
                wv.y = q3o * wv.y - sv * av.y;
                wv.z = q3o * wv.z - sv * av.z;
                wv.w = q3o * wv.w - sv * av.w;
                m34[e4] = wv;
            }
        }
        // ---- tail (e): W2 col update ----
        {
            float4* c4 = (float4*)m2c;
            const float4* a14 = (const float4*)a1f;
            #pragma unroll
            for (int k = 0; k < 2; k++) {
                int e4 = tid + 512 * k;
                int c = e4 >> 6, i4 = e4 & 63;
                float sv = LRc * o2[me * C1 + c];
                float4 wv = c4[e4], av = a14[i4];
                wv.x = q2o * wv.x - sv * av.x;
                wv.y = q2o * wv.y - sv * av.y;
                wv.z = q2o * wv.z - sv * av.z;
                wv.w = q2o * wv.w - sv * av.w;
                c4[e4] = wv;
            }
        }
        // ---- tail (f): W2 row update ----
        {
            float4* r4 = (float4*)m2r;
            const float4* o24 = (const float4*)o2;
            #pragma unroll
            for (int k = 0; k < 2; k++) {
                int e4 = tid + 512 * k;
                int r = e4 >> 6, j4 = e4 & 63;
                float sv = LRc * a1f[me * C1 + r];
                float4 wv = r4[e4], ov = o24[j4];
                wv.x = q2o * wv.x - sv * ov.x;
                wv.y = q2o * wv.y - sv * ov.y;
                wv.z = q2o * wv.z - sv * ov.z;
                wv.w = q2o * wv.w - sv * ov.w;
                r4[e4] = wv;
            }
        }
        __syncthreads();
    }

    CLUSTER_WAIT();   // pair the final arrive; delivers o1f(1023) + acc1r(1023) intact
    // final q1 via closed form (o1f(1023), acc1r in parity-1 buffer, ||x_1023||^2 in snx[1])
    {
        const float q1o = sq[0];
        const float* a1p = acc1 + 1 * Hh;
        float v0 = 0.f, v2 = 0.f;
        if (tid < Hh) { float ov = o1f[tid]; v0 = ov * a1p[tid]; v2 = ov * ov; }
        v0 = warp_sum(v0); v2 = warp_sum(v2);
        if (lane == 0) { sred[w * 9] = v0; sred[w * 9 + 1] = v2; }
        __syncthreads();
        if (w < 2) {
            float v = (lane < 16) ? sred[lane * 9 + w] : 0.f;
            v = warp_sum(v);
            if (lane == 0) sres[w] = v;
        }
        __syncthreads();
        if (tid == 0) {
            float S1 = q1o * q1o * sS[0] - 2.f * LRc * q1o * sres[0]
                     + LRc * LRc * snx[1] * sres[1];
            sq[0] = 1.f / fmaxf(sqrtf(S1), EPSc);
        }
        __syncthreads();
    }
    const float q1f = sq[0], q2f = sq[1], q3f = sq[2];

    // ---- write out: W1 | W2 | W3 (row-major), guarded, sanitized ----
    for (int idx = tid; idx < C1 * Dd; idx += T) {
        int c = idx & 15, r = idx >> 4;
        int o = r * Hh + me * C1 + c;
        if (o < out_size) out[o] = sanitize(q1f * m1[c * Dd + r]);
    }
    for (int idx = tid; idx < C1 * Hh; idx += T) {
        int c = idx & 15, i = idx >> 4;
        int o = Dd * Hh + i * Hh + me * C1 + c;
        if (o < out_size) out[o] = sanitize(q2f * m2c[c * Hh + i]);
    }
    for (int idx = tid; idx < 4 * Hh; idx += T) {
        int j = (int)me * 4 + (idx & 3), i = idx >> 2;
        int o = Dd * Hh + Hh * Hh + i * Oo + j;
        if (o < out_size) out[o] = sanitize(q3f * m3[j * Hh + i]);
    }
    for (int o = TOTAL_OUT + (int)me * T + tid; o < out_size; o += NC * T) out[o] = 0.f;
}

extern "C" void kernel_launch(void* const* d_in, const int* in_sizes, int n_in,
                              void* d_out, int out_size) {
    const float* X = 0; const float* Tg = 0;
    const float* W1 = 0; const float* b1 = 0;
    const float* W2 = 0; const float* b2 = 0;
    const float* W3 = 0; const float* b3 = 0;
    for (int i = 0; i < n_in; i++) {
        const float* p = (const float*)d_in[i];
        switch (in_sizes[i]) {
            case 1024 * 1024: X = p; break;
            case 1024 * 256:  W1 = p; break;
            case 256 * 256:   if (!Tg) Tg = p; else W2 = p; break;
            case 256 * 64:    W3 = p; break;
            case 256:         if (!b1) b1 = p; else b2 = p; break;
            case 64:          b3 = p; break;
            default: break;
        }
    }
    cudaFuncSetAttribute(train_kernel, cudaFuncAttributeMaxDynamicSharedMemorySize, SMEM_BYTES);
    cudaFuncSetAttribute(train_kernel, cudaFuncAttributeNonPortableClusterSizeAllowed, 1);

    cudaLaunchConfig_t cfg = {};
    cfg.gridDim = dim3(NC, 1, 1);
    cfg.blockDim = dim3(T, 1, 1);
    cfg.dynamicSmemBytes = SMEM_BYTES;
    cudaLaunchAttribute attrs[1];
    attrs[0].id = cudaLaunchAttributeClusterDimension;
    attrs[0].val.clusterDim.x = NC;
    attrs[0].val.clusterDim.y = 1;
    attrs[0].val.clusterDim.z = 1;
    cfg.attrs = attrs;
    cfg.numAttrs = 1;
    cudaLaunchKernelEx(&cfg, train_kernel, X, Tg, W1, b1, W2, b2, W3, b3,
                       (float*)d_out, out_size);
}